// round 7
// baseline (speedup 1.0000x reference)
#include <cuda_runtime.h>
#include <cuda_bf16.h>
#include <cstdint>

// 2-layer LSTM (H=32) + LayerNorm. B=4096, T=512, D=6.
// Round 7: cross-layer software pipeline. Iteration order:
//   L0-act(t) -> store h0 -> syncwarp -> L1-mm(t) -> L0-mm(t+1) -> L1-act(t)
// so L1's dependency stalls hide under L0-mm(t+1) FFMA2s and L1-act overlaps
// next iteration's L0-act. Carried L0 gate accumulators (32 regs).
// Base: 147 CTAs x 7 warps, BPW=4, tanh.approx, parity h-buffers, cp.async x.

#define T_STEPS 512
#define BATCH 4096
#define BPW 4
#define WARPS_PER_CTA 7
#define CTA_THREADS 224
#define NUM_CTAS 147
#define CHUNK 16
#define NCHUNK (T_STEPS / CHUNK)

#define SMEM_FLOATS (13056 + 3584 + 5376)
#define SMEM_BYTES (SMEM_FLOATS * 4)

__device__ __forceinline__ unsigned long long pk2(float lo, float hi) {
    unsigned long long r;
    asm("mov.b64 %0, {%1,%2};" : "=l"(r)
        : "r"(__float_as_uint(lo)), "r"(__float_as_uint(hi)));
    return r;
}
__device__ __forceinline__ float2 upk2(unsigned long long v) {
    unsigned int lo, hi;
    asm("mov.b64 {%0,%1}, %2;" : "=r"(lo), "=r"(hi) : "l"(v));
    return make_float2(__uint_as_float(lo), __uint_as_float(hi));
}
__device__ __forceinline__ unsigned long long ffma2(
    unsigned long long a, unsigned long long b, unsigned long long c) {
    unsigned long long d;
    asm("fma.rn.f32x2 %0, %1, %2, %3;" : "=l"(d) : "l"(a), "l"(b), "l"(c));
    return d;
}
__device__ __forceinline__ float tanhap(float x) {
    float r;
    asm("tanh.approx.f32 %0, %1;" : "=f"(r) : "f"(x));
    return r;
}
__device__ __forceinline__ float sigap(float x) {
    return fmaf(0.5f, tanhap(0.5f * x), 0.5f);
}
__device__ __forceinline__ void cp_async16(uint32_t s, const void* g) {
    asm volatile("cp.async.ca.shared.global [%0], [%1], 16;" :: "r"(s), "l"(g));
}

__global__ __launch_bounds__(CTA_THREADS, 1)
void lstm_enc_kernel(const float* __restrict__ x,
                     const float* __restrict__ W_ih0,
                     const float* __restrict__ W_hh0,
                     const float* __restrict__ b_ih0,
                     const float* __restrict__ b_hh0,
                     const float* __restrict__ W_ih1,
                     const float* __restrict__ W_hh1,
                     const float* __restrict__ b_ih1,
                     const float* __restrict__ b_hh1,
                     const float* __restrict__ ln_gamma,
                     const float* __restrict__ ln_beta,
                     float* __restrict__ out)
{
    extern __shared__ float smem[];
    float* sIh0if = smem;                 // [3kp][32j][4]
    float* sIh0go = sIh0if + 384;
    float* sHh0if = sIh0go + 384;         // [16kp][32j][4]
    float* sHh0go = sHh0if + 2048;
    float* sIh1if = sHh0go + 2048;
    float* sIh1go = sIh1if + 2048;
    float* sHh1if = sIh1go + 2048;
    float* sHh1go = sHh1if + 2048;
    float* hbuf   = sHh1go + 2048;        // 7 warps * 512
    float* xbuf   = hbuf + WARPS_PER_CTA * 512;

    const int tid = threadIdx.x;

    for (int i = tid; i < 512; i += CTA_THREADS) {
        int kp = i >> 5, j = i & 31;
        int k0 = 2 * kp, k1 = k0 + 1;
        ((float4*)sHh0if)[i] = make_float4(W_hh0[(j)*32+k0],    W_hh0[(j)*32+k1],
                                           W_hh0[(32+j)*32+k0], W_hh0[(32+j)*32+k1]);
        ((float4*)sHh0go)[i] = make_float4(W_hh0[(64+j)*32+k0], W_hh0[(64+j)*32+k1],
                                           W_hh0[(96+j)*32+k0], W_hh0[(96+j)*32+k1]);
        ((float4*)sIh1if)[i] = make_float4(W_ih1[(j)*32+k0],    W_ih1[(j)*32+k1],
                                           W_ih1[(32+j)*32+k0], W_ih1[(32+j)*32+k1]);
        ((float4*)sIh1go)[i] = make_float4(W_ih1[(64+j)*32+k0], W_ih1[(64+j)*32+k1],
                                           W_ih1[(96+j)*32+k0], W_ih1[(96+j)*32+k1]);
        ((float4*)sHh1if)[i] = make_float4(W_hh1[(j)*32+k0],    W_hh1[(j)*32+k1],
                                           W_hh1[(32+j)*32+k0], W_hh1[(32+j)*32+k1]);
        ((float4*)sHh1go)[i] = make_float4(W_hh1[(64+j)*32+k0], W_hh1[(64+j)*32+k1],
                                           W_hh1[(96+j)*32+k0], W_hh1[(96+j)*32+k1]);
    }
    for (int i = tid; i < 96; i += CTA_THREADS) {
        int kp = i >> 5, j = i & 31;
        int k0 = 2 * kp, k1 = k0 + 1;
        ((float4*)sIh0if)[i] = make_float4(W_ih0[(j)*6+k0],    W_ih0[(j)*6+k1],
                                           W_ih0[(32+j)*6+k0], W_ih0[(32+j)*6+k1]);
        ((float4*)sIh0go)[i] = make_float4(W_ih0[(64+j)*6+k0], W_ih0[(64+j)*6+k1],
                                           W_ih0[(96+j)*6+k0], W_ih0[(96+j)*6+k1]);
    }
    __syncthreads();

    const int wid = tid >> 5;
    const int j = tid & 31;
    const int task = blockIdx.x * WARPS_PER_CTA + wid;
    if (task * BPW >= BATCH) return;
    const int b0 = task * BPW;

    float* h0b = hbuf + wid * 512;
    float* h1b = h0b + 256;
    float* xs  = xbuf + wid * 768;

    #pragma unroll
    for (int p = 0; p < 2; p++)
        #pragma unroll
        for (int q = 0; q < BPW; q++) {
            h0b[p*128 + q*32 + j] = 0.0f;
            h1b[p*128 + q*32 + j] = 0.0f;
        }

    const float* xp[BPW];
    #pragma unroll
    for (int q = 0; q < BPW; q++) {
        int b = b0 + q; if (b > BATCH-1) b = BATCH-1;
        xp[q] = x + (size_t)b * (T_STEPS * 6);
    }

    float bi0 = b_ih0[j]    + b_hh0[j];
    float bf0 = b_ih0[32+j] + b_hh0[32+j];
    float bg0 = b_ih0[64+j] + b_hh0[64+j];
    float bo0 = b_ih0[96+j] + b_hh0[96+j];
    float bi1 = b_ih1[j]    + b_hh1[j];
    float bf1 = b_ih1[32+j] + b_hh1[32+j];
    float bg1 = b_ih1[64+j] + b_hh1[64+j];
    float bo1 = b_ih1[96+j] + b_hh1[96+j];

    float c0[BPW], c1[BPW], h1last[BPW];
    #pragma unroll
    for (int q = 0; q < BPW; q++) { c0[q]=0.f; c1[q]=0.f; h1last[q]=0.f; }

    const ulonglong2* Wih0if = (const ulonglong2*)sIh0if;
    const ulonglong2* Wih0go = (const ulonglong2*)sIh0go;
    const ulonglong2* Whh0if = (const ulonglong2*)sHh0if;
    const ulonglong2* Whh0go = (const ulonglong2*)sHh0go;
    const ulonglong2* Wih1if = (const ulonglong2*)sIh1if;
    const ulonglong2* Wih1go = (const ulonglong2*)sIh1go;
    const ulonglong2* Whh1if = (const ulonglong2*)sHh1if;
    const ulonglong2* Whh1go = (const ulonglong2*)sHh1go;

    // register-cache: Wih0 (3 kp) + Whh0 kp 0..3  (56 regs/lane)
    ulonglong2 rIf[3], rGo[3], rHif[4], rHgo[4];
    #pragma unroll
    for (int kp = 0; kp < 3; kp++) { rIf[kp] = Wih0if[kp*32 + j]; rGo[kp] = Wih0go[kp*32 + j]; }
    #pragma unroll
    for (int kp = 0; kp < 4; kp++) { rHif[kp] = Whh0if[kp*32 + j]; rHgo[kp] = Whh0go[kp*32 + j]; }

    const uint32_t xs_u32 = (uint32_t)__cvta_generic_to_shared(xs);

    // prologue: chunk 0 -> buffer 0
    {
        #pragma unroll
        for (int r = 0; r < 3; r++) {
            int idx = r * 32 + j;
            int q = idx / 24, f = idx % 24;
            cp_async16(xs_u32 + (uint32_t)(q*96 + f*4) * 4, xp[q] + f*4);
        }
        asm volatile("cp.async.commit_group;");
        asm volatile("cp.async.wait_group 0;");
        __syncwarp();
    }

    // carried L0 gate accumulators; prologue A(0): h0(-1)=0 so x-part only
    unsigned long long gai[BPW], gaf[BPW], gag[BPW], gao[BPW];
    #pragma unroll
    for (int q = 0; q < BPW; q++) {
        gai[q] = pk2(bi0, 0.f); gaf[q] = pk2(bf0, 0.f);
        gag[q] = pk2(bg0, 0.f); gao[q] = pk2(bo0, 0.f);
    }
    #pragma unroll
    for (int kp = 0; kp < 3; kp++) {
        #pragma unroll
        for (int q = 0; q < BPW; q++) {
            unsigned long long a = *(const unsigned long long*)(xs + q*96 + 2*kp);
            gai[q] = ffma2(a, rIf[kp].x, gai[q]);
            gaf[q] = ffma2(a, rIf[kp].y, gaf[q]);
            gag[q] = ffma2(a, rGo[kp].x, gag[q]);
            gao[q] = ffma2(a, rGo[kp].y, gao[q]);
        }
    }

    int buf = 0;
    for (int tc = 0; tc < NCHUNK; tc++) {
        #pragma unroll 1
        for (int lt = 0; lt < CHUNK; lt++) {
            const int t = tc * CHUNK + lt;
            const int p = t & 1;
            float*       h0wr = h0b + p * 128;
            const float* h1rd = h1b + (p^1) * 128;
            float*       h1wr = h1b + p * 128;

            // ===== L0 activations (from carried accums) -> store h0(t) =====
            #pragma unroll
            for (int q = 0; q < BPW; q++) {
                float2 ui = upk2(gai[q]), uf = upk2(gaf[q]);
                float2 ug = upk2(gag[q]), uo = upk2(gao[q]);
                float gi = sigap(ui.x + ui.y);
                float gf = sigap(uf.x + uf.y);
                float gg = tanhap(ug.x + ug.y);
                float go = sigap(uo.x + uo.y);
                c0[q] = gf * c0[q] + gi * gg;
                h0wr[q*32 + j] = go * tanhap(c0[q]);
            }
            __syncwarp();   // single per-step barrier

            // issue prefetch of next chunk early in the chunk
            if (lt == 0 && tc + 1 < NCHUNK) {
                uint32_t dst = xs_u32 + (uint32_t)((buf ^ 1) * 384) * 4;
                const int off = (tc + 1) * 96;
                #pragma unroll
                for (int r = 0; r < 3; r++) {
                    int idx = r * 32 + j;
                    int q = idx / 24, f = idx % 24;
                    cp_async16(dst + (uint32_t)(q*96 + f*4) * 4, xp[q] + off + f*4);
                }
                asm volatile("cp.async.commit_group;");
            }

            // ===== L1 matmul (t) =====
            unsigned long long ai[BPW], af[BPW], ag[BPW], ao[BPW];
            #pragma unroll
            for (int q = 0; q < BPW; q++) {
                ai[q] = pk2(bi1, 0.f); af[q] = pk2(bf1, 0.f);
                ag[q] = pk2(bg1, 0.f); ao[q] = pk2(bo1, 0.f);
            }
            #pragma unroll
            for (int m = 0; m < 8; m++) {
                ulonglong2 h[BPW];
                #pragma unroll
                for (int q = 0; q < BPW; q++)
                    h[q] = ((const ulonglong2*)(h0wr + q*32))[m];
                #pragma unroll
                for (int s = 0; s < 2; s++) {
                    int kp = 2*m + s;
                    ulonglong2 wif = Wih1if[kp*32 + j];
                    ulonglong2 wgo = Wih1go[kp*32 + j];
                    #pragma unroll
                    for (int q = 0; q < BPW; q++) {
                        unsigned long long a = s ? h[q].y : h[q].x;
                        ai[q] = ffma2(a, wif.x, ai[q]);
                        af[q] = ffma2(a, wif.y, af[q]);
                        ag[q] = ffma2(a, wgo.x, ag[q]);
                        ao[q] = ffma2(a, wgo.y, ao[q]);
                    }
                }
            }
            #pragma unroll
            for (int m = 0; m < 8; m++) {
                ulonglong2 h[BPW];
                #pragma unroll
                for (int q = 0; q < BPW; q++)
                    h[q] = ((const ulonglong2*)(h1rd + q*32))[m];
                #pragma unroll
                for (int s = 0; s < 2; s++) {
                    int kp = 2*m + s;
                    ulonglong2 wif = Whh1if[kp*32 + j];
                    ulonglong2 wgo = Whh1go[kp*32 + j];
                    #pragma unroll
                    for (int q = 0; q < BPW; q++) {
                        unsigned long long a = s ? h[q].y : h[q].x;
                        ai[q] = ffma2(a, wif.x, ai[q]);
                        af[q] = ffma2(a, wif.y, af[q]);
                        ag[q] = ffma2(a, wgo.x, ag[q]);
                        ao[q] = ffma2(a, wgo.y, ao[q]);
                    }
                }
            }

            // ===== L0 matmul (t+1): x(t+1) + h0(t) -> carried accums =====
            const float* xsrc;
            int lts;
            if (lt == CHUNK - 1) {
                asm volatile("cp.async.wait_group 0;");
                __syncwarp();
                xsrc = xs + (buf ^ 1) * 384;
                lts = 0;
            } else {
                xsrc = xs + buf * 384;
                lts = lt + 1;
            }
            #pragma unroll
            for (int q = 0; q < BPW; q++) {
                gai[q] = pk2(bi0, 0.f); gaf[q] = pk2(bf0, 0.f);
                gag[q] = pk2(bg0, 0.f); gao[q] = pk2(bo0, 0.f);
            }
            #pragma unroll
            for (int kp = 0; kp < 3; kp++) {
                #pragma unroll
                for (int q = 0; q < BPW; q++) {
                    unsigned long long a =
                        *(const unsigned long long*)(xsrc + q*96 + lts*6 + 2*kp);
                    gai[q] = ffma2(a, rIf[kp].x, gai[q]);
                    gaf[q] = ffma2(a, rIf[kp].y, gaf[q]);
                    gag[q] = ffma2(a, rGo[kp].x, gag[q]);
                    gao[q] = ffma2(a, rGo[kp].y, gao[q]);
                }
            }
            #pragma unroll
            for (int m = 0; m < 2; m++) {       // kp 0..3 register weights
                ulonglong2 h[BPW];
                #pragma unroll
                for (int q = 0; q < BPW; q++)
                    h[q] = ((const ulonglong2*)(h0wr + q*32))[m];
                #pragma unroll
                for (int s = 0; s < 2; s++) {
                    int kp = 2*m + s;
                    #pragma unroll
                    for (int q = 0; q < BPW; q++) {
                        unsigned long long a = s ? h[q].y : h[q].x;
                        gai[q] = ffma2(a, rHif[kp].x, gai[q]);
                        gaf[q] = ffma2(a, rHif[kp].y, gaf[q]);
                        gag[q] = ffma2(a, rHgo[kp].x, gag[q]);
                        gao[q] = ffma2(a, rHgo[kp].y, gao[q]);
                    }
                }
            }
            #pragma unroll
            for (int m = 2; m < 8; m++) {       // kp 4..15 smem weights
                ulonglong2 h[BPW];
                #pragma unroll
                for (int q = 0; q < BPW; q++)
                    h[q] = ((const ulonglong2*)(h0wr + q*32))[m];
                #pragma unroll
                for (int s = 0; s < 2; s++) {
                    int kp = 2*m + s;
                    ulonglong2 wif = Whh0if[kp*32 + j];
                    ulonglong2 wgo = Whh0go[kp*32 + j];
                    #pragma unroll
                    for (int q = 0; q < BPW; q++) {
                        unsigned long long a = s ? h[q].y : h[q].x;
                        gai[q] = ffma2(a, wif.x, gai[q]);
                        gaf[q] = ffma2(a, wif.y, gaf[q]);
                        gag[q] = ffma2(a, wgo.x, gag[q]);
                        gao[q] = ffma2(a, wgo.y, gao[q]);
                    }
                }
            }

            // ===== L1 activations (t) -> store h1(t) =====
            #pragma unroll
            for (int q = 0; q < BPW; q++) {
                float2 ui = upk2(ai[q]), uf = upk2(af[q]);
                float2 ug = upk2(ag[q]), uo = upk2(ao[q]);
                float gi = sigap(ui.x + ui.y);
                float gf = sigap(uf.x + uf.y);
                float gg = tanhap(ug.x + ug.y);
                float go = sigap(uo.x + uo.y);
                c1[q] = gf * c1[q] + gi * gg;
                float hn = go * tanhap(c1[q]);
                h1wr[q*32 + j] = hn;
                h1last[q] = hn;
            }
            // next iteration's post-L0 syncwarp orders h1 stores
        }
        buf ^= 1;
    }

    // ===== final LayerNorm over H=32 =====
    float g = ln_gamma[j];
    float be = ln_beta[j];
    #pragma unroll
    for (int q = 0; q < BPW; q++) {
        if (b0 + q >= BATCH) break;
        float v = h1last[q];
        float s = v;
        #pragma unroll
        for (int o2 = 16; o2 > 0; o2 >>= 1) s += __shfl_xor_sync(0xffffffffu, s, o2);
        float mu = s * (1.0f / 32.0f);
        float dv = v - mu;
        float qq = dv * dv;
        #pragma unroll
        for (int o2 = 16; o2 > 0; o2 >>= 1) qq += __shfl_xor_sync(0xffffffffu, qq, o2);
        float var = qq * (1.0f / 32.0f);
        out[(size_t)(b0 + q) * 32 + j] = dv * rsqrtf(var + 1e-5f) * g + be;
    }
}

extern "C" void kernel_launch(void* const* d_in, const int* in_sizes, int n_in,
                              void* d_out, int out_size)
{
    const float* x      = (const float*)d_in[0];
    const float* W_ih0  = (const float*)d_in[1];
    const float* W_hh0  = (const float*)d_in[2];
    const float* b_ih0  = (const float*)d_in[3];
    const float* b_hh0  = (const float*)d_in[4];
    const float* W_ih1  = (const float*)d_in[5];
    const float* W_hh1  = (const float*)d_in[6];
    const float* b_ih1  = (const float*)d_in[7];
    const float* b_hh1  = (const float*)d_in[8];
    const float* ln_g   = (const float*)d_in[9];
    const float* ln_b   = (const float*)d_in[10];
    float* out = (float*)d_out;

    cudaFuncSetAttribute(lstm_enc_kernel,
                         cudaFuncAttributeMaxDynamicSharedMemorySize, SMEM_BYTES);
    lstm_enc_kernel<<<NUM_CTAS, CTA_THREADS, SMEM_BYTES>>>(
        x, W_ih0, W_hh0, b_ih0, b_hh0, W_ih1, W_hh1, b_ih1, b_hh1,
        ln_g, ln_b, out);
}

// round 11
// speedup vs baseline: 1.0989x; 1.0989x over previous
#include <cuda_runtime.h>
#include <cuda_bf16.h>
#include <cstdint>

// 2-layer LSTM (H=32) + LayerNorm. B=4096, T=512, D=6.
// Round 8: R7 cross-layer pipeline, register-funded: only Wih0 cached in
// registers (24 regs); Whh0 fully from smem. Avoids the R7 spill (regs=255).
// Order: L0-act(t) -> store h0 -> sync -> L1-mm(t) -> L0-mm(t+1) -> L1-act(t).
// Base: 147 CTAs x 7 warps, BPW=4, tanh.approx, parity h-buffers, cp.async x.

#define T_STEPS 512
#define BATCH 4096
#define BPW 4
#define WARPS_PER_CTA 7
#define CTA_THREADS 224
#define NUM_CTAS 147
#define CHUNK 16
#define NCHUNK (T_STEPS / CHUNK)

#define SMEM_FLOATS (13056 + 3584 + 5376)
#define SMEM_BYTES (SMEM_FLOATS * 4)

__device__ __forceinline__ unsigned long long pk2(float lo, float hi) {
    unsigned long long r;
    asm("mov.b64 %0, {%1,%2};" : "=l"(r)
        : "r"(__float_as_uint(lo)), "r"(__float_as_uint(hi)));
    return r;
}
__device__ __forceinline__ float2 upk2(unsigned long long v) {
    unsigned int lo, hi;
    asm("mov.b64 {%0,%1}, %2;" : "=r"(lo), "=r"(hi) : "l"(v));
    return make_float2(__uint_as_float(lo), __uint_as_float(hi));
}
__device__ __forceinline__ unsigned long long ffma2(
    unsigned long long a, unsigned long long b, unsigned long long c) {
    unsigned long long d;
    asm("fma.rn.f32x2 %0, %1, %2, %3;" : "=l"(d) : "l"(a), "l"(b), "l"(c));
    return d;
}
__device__ __forceinline__ float tanhap(float x) {
    float r;
    asm("tanh.approx.f32 %0, %1;" : "=f"(r) : "f"(x));
    return r;
}
__device__ __forceinline__ float sigap(float x) {
    return fmaf(0.5f, tanhap(0.5f * x), 0.5f);
}
__device__ __forceinline__ void cp_async16(uint32_t s, const void* g) {
    asm volatile("cp.async.ca.shared.global [%0], [%1], 16;" :: "r"(s), "l"(g));
}

__global__ __launch_bounds__(CTA_THREADS, 1)
void lstm_enc_kernel(const float* __restrict__ x,
                     const float* __restrict__ W_ih0,
                     const float* __restrict__ W_hh0,
                     const float* __restrict__ b_ih0,
                     const float* __restrict__ b_hh0,
                     const float* __restrict__ W_ih1,
                     const float* __restrict__ W_hh1,
                     const float* __restrict__ b_ih1,
                     const float* __restrict__ b_hh1,
                     const float* __restrict__ ln_gamma,
                     const float* __restrict__ ln_beta,
                     float* __restrict__ out)
{
    extern __shared__ float smem[];
    float* sIh0if = smem;                 // [3kp][32j][4]
    float* sIh0go = sIh0if + 384;
    float* sHh0if = sIh0go + 384;         // [16kp][32j][4]
    float* sHh0go = sHh0if + 2048;
    float* sIh1if = sHh0go + 2048;
    float* sIh1go = sIh1if + 2048;
    float* sHh1if = sIh1go + 2048;
    float* sHh1go = sHh1if + 2048;
    float* hbuf   = sHh1go + 2048;        // 7 warps * 512
    float* xbuf   = hbuf + WARPS_PER_CTA * 512;

    const int tid = threadIdx.x;

    for (int i = tid; i < 512; i += CTA_THREADS) {
        int kp = i >> 5, j = i & 31;
        int k0 = 2 * kp, k1 = k0 + 1;
        ((float4*)sHh0if)[i] = make_float4(W_hh0[(j)*32+k0],    W_hh0[(j)*32+k1],
                                           W_hh0[(32+j)*32+k0], W_hh0[(32+j)*32+k1]);
        ((float4*)sHh0go)[i] = make_float4(W_hh0[(64+j)*32+k0], W_hh0[(64+j)*32+k1],
                                           W_hh0[(96+j)*32+k0], W_hh0[(96+j)*32+k1]);
        ((float4*)sIh1if)[i] = make_float4(W_ih1[(j)*32+k0],    W_ih1[(j)*32+k1],
                                           W_ih1[(32+j)*32+k0], W_ih1[(32+j)*32+k1]);
        ((float4*)sIh1go)[i] = make_float4(W_ih1[(64+j)*32+k0], W_ih1[(64+j)*32+k1],
                                           W_ih1[(96+j)*32+k0], W_ih1[(96+j)*32+k1]);
        ((float4*)sHh1if)[i] = make_float4(W_hh1[(j)*32+k0],    W_hh1[(j)*32+k1],
                                           W_hh1[(32+j)*32+k0], W_hh1[(32+j)*32+k1]);
        ((float4*)sHh1go)[i] = make_float4(W_hh1[(64+j)*32+k0], W_hh1[(64+j)*32+k1],
                                           W_hh1[(96+j)*32+k0], W_hh1[(96+j)*32+k1]);
    }
    for (int i = tid; i < 96; i += CTA_THREADS) {
        int kp = i >> 5, j = i & 31;
        int k0 = 2 * kp, k1 = k0 + 1;
        ((float4*)sIh0if)[i] = make_float4(W_ih0[(j)*6+k0],    W_ih0[(j)*6+k1],
                                           W_ih0[(32+j)*6+k0], W_ih0[(32+j)*6+k1]);
        ((float4*)sIh0go)[i] = make_float4(W_ih0[(64+j)*6+k0], W_ih0[(64+j)*6+k1],
                                           W_ih0[(96+j)*6+k0], W_ih0[(96+j)*6+k1]);
    }
    __syncthreads();

    const int wid = tid >> 5;
    const int j = tid & 31;
    const int task = blockIdx.x * WARPS_PER_CTA + wid;
    if (task * BPW >= BATCH) return;
    const int b0 = task * BPW;

    float* h0b = hbuf + wid * 512;
    float* h1b = h0b + 256;
    float* xs  = xbuf + wid * 768;

    #pragma unroll
    for (int p = 0; p < 2; p++)
        #pragma unroll
        for (int q = 0; q < BPW; q++) {
            h0b[p*128 + q*32 + j] = 0.0f;
            h1b[p*128 + q*32 + j] = 0.0f;
        }

    const float* xp[BPW];
    #pragma unroll
    for (int q = 0; q < BPW; q++) {
        int b = b0 + q; if (b > BATCH-1) b = BATCH-1;
        xp[q] = x + (size_t)b * (T_STEPS * 6);
    }

    float bi0 = b_ih0[j]    + b_hh0[j];
    float bf0 = b_ih0[32+j] + b_hh0[32+j];
    float bg0 = b_ih0[64+j] + b_hh0[64+j];
    float bo0 = b_ih0[96+j] + b_hh0[96+j];
    float bi1 = b_ih1[j]    + b_hh1[j];
    float bf1 = b_ih1[32+j] + b_hh1[32+j];
    float bg1 = b_ih1[64+j] + b_hh1[64+j];
    float bo1 = b_ih1[96+j] + b_hh1[96+j];

    float c0[BPW], c1[BPW], h1last[BPW];
    #pragma unroll
    for (int q = 0; q < BPW; q++) { c0[q]=0.f; c1[q]=0.f; h1last[q]=0.f; }

    const ulonglong2* Wih0if = (const ulonglong2*)sIh0if;
    const ulonglong2* Wih0go = (const ulonglong2*)sIh0go;
    const ulonglong2* Whh0if = (const ulonglong2*)sHh0if;
    const ulonglong2* Whh0go = (const ulonglong2*)sHh0go;
    const ulonglong2* Wih1if = (const ulonglong2*)sIh1if;
    const ulonglong2* Wih1go = (const ulonglong2*)sIh1go;
    const ulonglong2* Whh1if = (const ulonglong2*)sHh1if;
    const ulonglong2* Whh1go = (const ulonglong2*)sHh1go;

    // register-cache: Wih0 only (24 regs/lane)
    ulonglong2 rIf[3], rGo[3];
    #pragma unroll
    for (int kp = 0; kp < 3; kp++) { rIf[kp] = Wih0if[kp*32 + j]; rGo[kp] = Wih0go[kp*32 + j]; }

    const uint32_t xs_u32 = (uint32_t)__cvta_generic_to_shared(xs);

    // prologue: chunk 0 -> buffer 0
    {
        #pragma unroll
        for (int r = 0; r < 3; r++) {
            int idx = r * 32 + j;
            int q = idx / 24, f = idx % 24;
            cp_async16(xs_u32 + (uint32_t)(q*96 + f*4) * 4, xp[q] + f*4);
        }
        asm volatile("cp.async.commit_group;");
        asm volatile("cp.async.wait_group 0;");
        __syncwarp();
    }

    // carried L0 gate accumulators; prologue A(0): h0(-1)=0 so x-part only
    unsigned long long gai[BPW], gaf[BPW], gag[BPW], gao[BPW];
    #pragma unroll
    for (int q = 0; q < BPW; q++) {
        gai[q] = pk2(bi0, 0.f); gaf[q] = pk2(bf0, 0.f);
        gag[q] = pk2(bg0, 0.f); gao[q] = pk2(bo0, 0.f);
    }
    #pragma unroll
    for (int kp = 0; kp < 3; kp++) {
        #pragma unroll
        for (int q = 0; q < BPW; q++) {
            unsigned long long a = *(const unsigned long long*)(xs + q*96 + 2*kp);
            gai[q] = ffma2(a, rIf[kp].x, gai[q]);
            gaf[q] = ffma2(a, rIf[kp].y, gaf[q]);
            gag[q] = ffma2(a, rGo[kp].x, gag[q]);
            gao[q] = ffma2(a, rGo[kp].y, gao[q]);
        }
    }

    int buf = 0;
    for (int tc = 0; tc < NCHUNK; tc++) {
        #pragma unroll 1
        for (int lt = 0; lt < CHUNK; lt++) {
            const int t = tc * CHUNK + lt;
            const int p = t & 1;
            float*       h0wr = h0b + p * 128;
            const float* h1rd = h1b + (p^1) * 128;
            float*       h1wr = h1b + p * 128;

            // ===== L0 activations (from carried accums) -> store h0(t) =====
            #pragma unroll
            for (int q = 0; q < BPW; q++) {
                float2 ui = upk2(gai[q]), uf = upk2(gaf[q]);
                float2 ug = upk2(gag[q]), uo = upk2(gao[q]);
                float gi = sigap(ui.x + ui.y);
                float gf = sigap(uf.x + uf.y);
                float gg = tanhap(ug.x + ug.y);
                float go = sigap(uo.x + uo.y);
                c0[q] = gf * c0[q] + gi * gg;
                h0wr[q*32 + j] = go * tanhap(c0[q]);
            }
            __syncwarp();   // single per-step barrier

            // issue prefetch of next chunk early in the chunk
            if (lt == 0 && tc + 1 < NCHUNK) {
                uint32_t dst = xs_u32 + (uint32_t)((buf ^ 1) * 384) * 4;
                const int off = (tc + 1) * 96;
                #pragma unroll
                for (int r = 0; r < 3; r++) {
                    int idx = r * 32 + j;
                    int q = idx / 24, f = idx % 24;
                    cp_async16(dst + (uint32_t)(q*96 + f*4) * 4, xp[q] + off + f*4);
                }
                asm volatile("cp.async.commit_group;");
            }

            // ===== L1 matmul (t) =====
            unsigned long long ai[BPW], af[BPW], ag[BPW], ao[BPW];
            #pragma unroll
            for (int q = 0; q < BPW; q++) {
                ai[q] = pk2(bi1, 0.f); af[q] = pk2(bf1, 0.f);
                ag[q] = pk2(bg1, 0.f); ao[q] = pk2(bo1, 0.f);
            }
            #pragma unroll
            for (int m = 0; m < 8; m++) {
                ulonglong2 h[BPW];
                #pragma unroll
                for (int q = 0; q < BPW; q++)
                    h[q] = ((const ulonglong2*)(h0wr + q*32))[m];
                #pragma unroll
                for (int s = 0; s < 2; s++) {
                    int kp = 2*m + s;
                    ulonglong2 wif = Wih1if[kp*32 + j];
                    ulonglong2 wgo = Wih1go[kp*32 + j];
                    #pragma unroll
                    for (int q = 0; q < BPW; q++) {
                        unsigned long long a = s ? h[q].y : h[q].x;
                        ai[q] = ffma2(a, wif.x, ai[q]);
                        af[q] = ffma2(a, wif.y, af[q]);
                        ag[q] = ffma2(a, wgo.x, ag[q]);
                        ao[q] = ffma2(a, wgo.y, ao[q]);
                    }
                }
            }
            #pragma unroll
            for (int m = 0; m < 8; m++) {
                ulonglong2 h[BPW];
                #pragma unroll
                for (int q = 0; q < BPW; q++)
                    h[q] = ((const ulonglong2*)(h1rd + q*32))[m];
                #pragma unroll
                for (int s = 0; s < 2; s++) {
                    int kp = 2*m + s;
                    ulonglong2 wif = Whh1if[kp*32 + j];
                    ulonglong2 wgo = Whh1go[kp*32 + j];
                    #pragma unroll
                    for (int q = 0; q < BPW; q++) {
                        unsigned long long a = s ? h[q].y : h[q].x;
                        ai[q] = ffma2(a, wif.x, ai[q]);
                        af[q] = ffma2(a, wif.y, af[q]);
                        ag[q] = ffma2(a, wgo.x, ag[q]);
                        ao[q] = ffma2(a, wgo.y, ao[q]);
                    }
                }
            }

            // ===== L0 matmul (t+1): x(t+1) + h0(t) -> carried accums =====
            const float* xsrc;
            int lts;
            if (lt == CHUNK - 1) {
                asm volatile("cp.async.wait_group 0;");
                __syncwarp();
                xsrc = xs + (buf ^ 1) * 384;
                lts = 0;
            } else {
                xsrc = xs + buf * 384;
                lts = lt + 1;
            }
            #pragma unroll
            for (int q = 0; q < BPW; q++) {
                gai[q] = pk2(bi0, 0.f); gaf[q] = pk2(bf0, 0.f);
                gag[q] = pk2(bg0, 0.f); gao[q] = pk2(bo0, 0.f);
            }
            #pragma unroll
            for (int kp = 0; kp < 3; kp++) {
                #pragma unroll
                for (int q = 0; q < BPW; q++) {
                    unsigned long long a =
                        *(const unsigned long long*)(xsrc + q*96 + lts*6 + 2*kp);
                    gai[q] = ffma2(a, rIf[kp].x, gai[q]);
                    gaf[q] = ffma2(a, rIf[kp].y, gaf[q]);
                    gag[q] = ffma2(a, rGo[kp].x, gag[q]);
                    gao[q] = ffma2(a, rGo[kp].y, gao[q]);
                }
            }
            #pragma unroll
            for (int m = 0; m < 8; m++) {
                ulonglong2 h[BPW];
                #pragma unroll
                for (int q = 0; q < BPW; q++)
                    h[q] = ((const ulonglong2*)(h0wr + q*32))[m];
                #pragma unroll
                for (int s = 0; s < 2; s++) {
                    int kp = 2*m + s;
                    ulonglong2 wif = Whh0if[kp*32 + j];
                    ulonglong2 wgo = Whh0go[kp*32 + j];
                    #pragma unroll
                    for (int q = 0; q < BPW; q++) {
                        unsigned long long a = s ? h[q].y : h[q].x;
                        gai[q] = ffma2(a, wif.x, gai[q]);
                        gaf[q] = ffma2(a, wif.y, gaf[q]);
                        gag[q] = ffma2(a, wgo.x, gag[q]);
                        gao[q] = ffma2(a, wgo.y, gao[q]);
                    }
                }
            }

            // ===== L1 activations (t) -> store h1(t) =====
            #pragma unroll
            for (int q = 0; q < BPW; q++) {
                float2 ui = upk2(ai[q]), uf = upk2(af[q]);
                float2 ug = upk2(ag[q]), uo = upk2(ao[q]);
                float gi = sigap(ui.x + ui.y);
                float gf = sigap(uf.x + uf.y);
                float gg = tanhap(ug.x + ug.y);
                float go = sigap(uo.x + uo.y);
                c1[q] = gf * c1[q] + gi * gg;
                float hn = go * tanhap(c1[q]);
                h1wr[q*32 + j] = hn;
                h1last[q] = hn;
            }
            // next iteration's post-L0 syncwarp orders h1 stores
        }
        buf ^= 1;
    }

    // ===== final LayerNorm over H=32 =====
    float g = ln_gamma[j];
    float be = ln_beta[j];
    #pragma unroll
    for (int q = 0; q < BPW; q++) {
        if (b0 + q >= BATCH) break;
        float v = h1last[q];
        float s = v;
        #pragma unroll
        for (int o2 = 16; o2 > 0; o2 >>= 1) s += __shfl_xor_sync(0xffffffffu, s, o2);
        float mu = s * (1.0f / 32.0f);
        float dv = v - mu;
        float qq = dv * dv;
        #pragma unroll
        for (int o2 = 16; o2 > 0; o2 >>= 1) qq += __shfl_xor_sync(0xffffffffu, qq, o2);
        float var = qq * (1.0f / 32.0f);
        out[(size_t)(b0 + q) * 32 + j] = dv * rsqrtf(var + 1e-5f) * g + be;
    }
}

extern "C" void kernel_launch(void* const* d_in, const int* in_sizes, int n_in,
                              void* d_out, int out_size)
{
    const float* x      = (const float*)d_in[0];
    const float* W_ih0  = (const float*)d_in[1];
    const float* W_hh0  = (const float*)d_in[2];
    const float* b_ih0  = (const float*)d_in[3];
    const float* b_hh0  = (const float*)d_in[4];
    const float* W_ih1  = (const float*)d_in[5];
    const float* W_hh1  = (const float*)d_in[6];
    const float* b_ih1  = (const float*)d_in[7];
    const float* b_hh1  = (const float*)d_in[8];
    const float* ln_g   = (const float*)d_in[9];
    const float* ln_b   = (const float*)d_in[10];
    float* out = (float*)d_out;

    cudaFuncSetAttribute(lstm_enc_kernel,
                         cudaFuncAttributeMaxDynamicSharedMemorySize, SMEM_BYTES);
    lstm_enc_kernel<<<NUM_CTAS, CTA_THREADS, SMEM_BYTES>>>(
        x, W_ih0, W_hh0, b_ih0, b_hh0, W_ih1, W_hh1, b_ih1, b_hh1,
        ln_g, ln_b, out);
}

// round 13
// speedup vs baseline: 1.1003x; 1.0012x over previous
#include <cuda_runtime.h>
#include <cuda_bf16.h>
#include <cstdint>

// 2-layer LSTM (H=32) + LayerNorm. B=4096, T=512, D=6.
// Round 8: R7 cross-layer pipeline, register-funded: only Wih0 cached in
// registers (24 regs); Whh0 fully from smem. Avoids the R7 spill (regs=255).
// Order: L0-act(t) -> store h0 -> sync -> L1-mm(t) -> L0-mm(t+1) -> L1-act(t).
// Base: 147 CTAs x 7 warps, BPW=4, tanh.approx, parity h-buffers, cp.async x.

#define T_STEPS 512
#define BATCH 4096
#define BPW 4
#define WARPS_PER_CTA 7
#define CTA_THREADS 224
#define NUM_CTAS 147
#define CHUNK 16
#define NCHUNK (T_STEPS / CHUNK)

#define SMEM_FLOATS (13056 + 3584 + 5376)
#define SMEM_BYTES (SMEM_FLOATS * 4)

__device__ __forceinline__ unsigned long long pk2(float lo, float hi) {
    unsigned long long r;
    asm("mov.b64 %0, {%1,%2};" : "=l"(r)
        : "r"(__float_as_uint(lo)), "r"(__float_as_uint(hi)));
    return r;
}
__device__ __forceinline__ float2 upk2(unsigned long long v) {
    unsigned int lo, hi;
    asm("mov.b64 {%0,%1}, %2;" : "=r"(lo), "=r"(hi) : "l"(v));
    return make_float2(__uint_as_float(lo), __uint_as_float(hi));
}
__device__ __forceinline__ unsigned long long ffma2(
    unsigned long long a, unsigned long long b, unsigned long long c) {
    unsigned long long d;
    asm("fma.rn.f32x2 %0, %1, %2, %3;" : "=l"(d) : "l"(a), "l"(b), "l"(c));
    return d;
}
__device__ __forceinline__ float tanhap(float x) {
    float r;
    asm("tanh.approx.f32 %0, %1;" : "=f"(r) : "f"(x));
    return r;
}
__device__ __forceinline__ float sigap(float x) {
    return fmaf(0.5f, tanhap(0.5f * x), 0.5f);
}
__device__ __forceinline__ void cp_async16(uint32_t s, const void* g) {
    asm volatile("cp.async.ca.shared.global [%0], [%1], 16;" :: "r"(s), "l"(g));
}

__global__ __launch_bounds__(CTA_THREADS, 1)
void lstm_enc_kernel(const float* __restrict__ x,
                     const float* __restrict__ W_ih0,
                     const float* __restrict__ W_hh0,
                     const float* __restrict__ b_ih0,
                     const float* __restrict__ b_hh0,
                     const float* __restrict__ W_ih1,
                     const float* __restrict__ W_hh1,
                     const float* __restrict__ b_ih1,
                     const float* __restrict__ b_hh1,
                     const float* __restrict__ ln_gamma,
                     const float* __restrict__ ln_beta,
                     float* __restrict__ out)
{
    extern __shared__ float smem[];
    float* sIh0if = smem;                 // [3kp][32j][4]
    float* sIh0go = sIh0if + 384;
    float* sHh0if = sIh0go + 384;         // [16kp][32j][4]
    float* sHh0go = sHh0if + 2048;
    float* sIh1if = sHh0go + 2048;
    float* sIh1go = sIh1if + 2048;
    float* sHh1if = sIh1go + 2048;
    float* sHh1go = sHh1if + 2048;
    float* hbuf   = sHh1go + 2048;        // 7 warps * 512
    float* xbuf   = hbuf + WARPS_PER_CTA * 512;

    const int tid = threadIdx.x;

    for (int i = tid; i < 512; i += CTA_THREADS) {
        int kp = i >> 5, j = i & 31;
        int k0 = 2 * kp, k1 = k0 + 1;
        ((float4*)sHh0if)[i] = make_float4(W_hh0[(j)*32+k0],    W_hh0[(j)*32+k1],
                                           W_hh0[(32+j)*32+k0], W_hh0[(32+j)*32+k1]);
        ((float4*)sHh0go)[i] = make_float4(W_hh0[(64+j)*32+k0], W_hh0[(64+j)*32+k1],
                                           W_hh0[(96+j)*32+k0], W_hh0[(96+j)*32+k1]);
        ((float4*)sIh1if)[i] = make_float4(W_ih1[(j)*32+k0],    W_ih1[(j)*32+k1],
                                           W_ih1[(32+j)*32+k0], W_ih1[(32+j)*32+k1]);
        ((float4*)sIh1go)[i] = make_float4(W_ih1[(64+j)*32+k0], W_ih1[(64+j)*32+k1],
                                           W_ih1[(96+j)*32+k0], W_ih1[(96+j)*32+k1]);
        ((float4*)sHh1if)[i] = make_float4(W_hh1[(j)*32+k0],    W_hh1[(j)*32+k1],
                                           W_hh1[(32+j)*32+k0], W_hh1[(32+j)*32+k1]);
        ((float4*)sHh1go)[i] = make_float4(W_hh1[(64+j)*32+k0], W_hh1[(64+j)*32+k1],
                                           W_hh1[(96+j)*32+k0], W_hh1[(96+j)*32+k1]);
    }
    for (int i = tid; i < 96; i += CTA_THREADS) {
        int kp = i >> 5, j = i & 31;
        int k0 = 2 * kp, k1 = k0 + 1;
        ((float4*)sIh0if)[i] = make_float4(W_ih0[(j)*6+k0],    W_ih0[(j)*6+k1],
                                           W_ih0[(32+j)*6+k0], W_ih0[(32+j)*6+k1]);
        ((float4*)sIh0go)[i] = make_float4(W_ih0[(64+j)*6+k0], W_ih0[(64+j)*6+k1],
                                           W_ih0[(96+j)*6+k0], W_ih0[(96+j)*6+k1]);
    }
    __syncthreads();

    const int wid = tid >> 5;
    const int j = tid & 31;
    const int task = blockIdx.x * WARPS_PER_CTA + wid;
    if (task * BPW >= BATCH) return;
    const int b0 = task * BPW;

    float* h0b = hbuf + wid * 512;
    float* h1b = h0b + 256;
    float* xs  = xbuf + wid * 768;

    #pragma unroll
    for (int p = 0; p < 2; p++)
        #pragma unroll
        for (int q = 0; q < BPW; q++) {
            h0b[p*128 + q*32 + j] = 0.0f;
            h1b[p*128 + q*32 + j] = 0.0f;
        }

    const float* xp[BPW];
    #pragma unroll
    for (int q = 0; q < BPW; q++) {
        int b = b0 + q; if (b > BATCH-1) b = BATCH-1;
        xp[q] = x + (size_t)b * (T_STEPS * 6);
    }

    float bi0 = b_ih0[j]    + b_hh0[j];
    float bf0 = b_ih0[32+j] + b_hh0[32+j];
    float bg0 = b_ih0[64+j] + b_hh0[64+j];
    float bo0 = b_ih0[96+j] + b_hh0[96+j];
    float bi1 = b_ih1[j]    + b_hh1[j];
    float bf1 = b_ih1[32+j] + b_hh1[32+j];
    float bg1 = b_ih1[64+j] + b_hh1[64+j];
    float bo1 = b_ih1[96+j] + b_hh1[96+j];

    float c0[BPW], c1[BPW], h1last[BPW];
    #pragma unroll
    for (int q = 0; q < BPW; q++) { c0[q]=0.f; c1[q]=0.f; h1last[q]=0.f; }

    const ulonglong2* Wih0if = (const ulonglong2*)sIh0if;
    const ulonglong2* Wih0go = (const ulonglong2*)sIh0go;
    const ulonglong2* Whh0if = (const ulonglong2*)sHh0if;
    const ulonglong2* Whh0go = (const ulonglong2*)sHh0go;
    const ulonglong2* Wih1if = (const ulonglong2*)sIh1if;
    const ulonglong2* Wih1go = (const ulonglong2*)sIh1go;
    const ulonglong2* Whh1if = (const ulonglong2*)sHh1if;
    const ulonglong2* Whh1go = (const ulonglong2*)sHh1go;

    // register-cache: Wih0 only (24 regs/lane)
    ulonglong2 rIf[3], rGo[3];
    #pragma unroll
    for (int kp = 0; kp < 3; kp++) { rIf[kp] = Wih0if[kp*32 + j]; rGo[kp] = Wih0go[kp*32 + j]; }

    const uint32_t xs_u32 = (uint32_t)__cvta_generic_to_shared(xs);

    // prologue: chunk 0 -> buffer 0
    {
        #pragma unroll
        for (int r = 0; r < 3; r++) {
            int idx = r * 32 + j;
            int q = idx / 24, f = idx % 24;
            cp_async16(xs_u32 + (uint32_t)(q*96 + f*4) * 4, xp[q] + f*4);
        }
        asm volatile("cp.async.commit_group;");
        asm volatile("cp.async.wait_group 0;");
        __syncwarp();
    }

    // carried L0 gate accumulators; prologue A(0): h0(-1)=0 so x-part only
    unsigned long long gai[BPW], gaf[BPW], gag[BPW], gao[BPW];
    #pragma unroll
    for (int q = 0; q < BPW; q++) {
        gai[q] = pk2(bi0, 0.f); gaf[q] = pk2(bf0, 0.f);
        gag[q] = pk2(bg0, 0.f); gao[q] = pk2(bo0, 0.f);
    }
    #pragma unroll
    for (int kp = 0; kp < 3; kp++) {
        #pragma unroll
        for (int q = 0; q < BPW; q++) {
            unsigned long long a = *(const unsigned long long*)(xs + q*96 + 2*kp);
            gai[q] = ffma2(a, rIf[kp].x, gai[q]);
            gaf[q] = ffma2(a, rIf[kp].y, gaf[q]);
            gag[q] = ffma2(a, rGo[kp].x, gag[q]);
            gao[q] = ffma2(a, rGo[kp].y, gao[q]);
        }
    }

    int buf = 0;
    for (int tc = 0; tc < NCHUNK; tc++) {
        #pragma unroll 1
        for (int lt = 0; lt < CHUNK; lt++) {
            const int t = tc * CHUNK + lt;
            const int p = t & 1;
            float*       h0wr = h0b + p * 128;
            const float* h1rd = h1b + (p^1) * 128;
            float*       h1wr = h1b + p * 128;

            // ===== L0 activations (from carried accums) -> store h0(t) =====
            #pragma unroll
            for (int q = 0; q < BPW; q++) {
                float2 ui = upk2(gai[q]), uf = upk2(gaf[q]);
                float2 ug = upk2(gag[q]), uo = upk2(gao[q]);
                float gi = sigap(ui.x + ui.y);
                float gf = sigap(uf.x + uf.y);
                float gg = tanhap(ug.x + ug.y);
                float go = sigap(uo.x + uo.y);
                c0[q] = gf * c0[q] + gi * gg;
                h0wr[q*32 + j] = go * tanhap(c0[q]);
            }
            __syncwarp();   // single per-step barrier

            // issue prefetch of next chunk early in the chunk
            if (lt == 0 && tc + 1 < NCHUNK) {
                uint32_t dst = xs_u32 + (uint32_t)((buf ^ 1) * 384) * 4;
                const int off = (tc + 1) * 96;
                #pragma unroll
                for (int r = 0; r < 3; r++) {
                    int idx = r * 32 + j;
                    int q = idx / 24, f = idx % 24;
                    cp_async16(dst + (uint32_t)(q*96 + f*4) * 4, xp[q] + off + f*4);
                }
                asm volatile("cp.async.commit_group;");
            }

            // ===== L1 matmul (t) =====
            unsigned long long ai[BPW], af[BPW], ag[BPW], ao[BPW];
            #pragma unroll
            for (int q = 0; q < BPW; q++) {
                ai[q] = pk2(bi1, 0.f); af[q] = pk2(bf1, 0.f);
                ag[q] = pk2(bg1, 0.f); ao[q] = pk2(bo1, 0.f);
            }
            #pragma unroll
            for (int m = 0; m < 8; m++) {
                ulonglong2 h[BPW];
                #pragma unroll
                for (int q = 0; q < BPW; q++)
                    h[q] = ((const ulonglong2*)(h0wr + q*32))[m];
                #pragma unroll
                for (int s = 0; s < 2; s++) {
                    int kp = 2*m + s;
                    ulonglong2 wif = Wih1if[kp*32 + j];
                    ulonglong2 wgo = Wih1go[kp*32 + j];
                    #pragma unroll
                    for (int q = 0; q < BPW; q++) {
                        unsigned long long a = s ? h[q].y : h[q].x;
                        ai[q] = ffma2(a, wif.x, ai[q]);
                        af[q] = ffma2(a, wif.y, af[q]);
                        ag[q] = ffma2(a, wgo.x, ag[q]);
                        ao[q] = ffma2(a, wgo.y, ao[q]);
                    }
                }
            }
            #pragma unroll
            for (int m = 0; m < 8; m++) {
                ulonglong2 h[BPW];
                #pragma unroll
                for (int q = 0; q < BPW; q++)
                    h[q] = ((const ulonglong2*)(h1rd + q*32))[m];
                #pragma unroll
                for (int s = 0; s < 2; s++) {
                    int kp = 2*m + s;
                    ulonglong2 wif = Whh1if[kp*32 + j];
                    ulonglong2 wgo = Whh1go[kp*32 + j];
                    #pragma unroll
                    for (int q = 0; q < BPW; q++) {
                        unsigned long long a = s ? h[q].y : h[q].x;
                        ai[q] = ffma2(a, wif.x, ai[q]);
                        af[q] = ffma2(a, wif.y, af[q]);
                        ag[q] = ffma2(a, wgo.x, ag[q]);
                        ao[q] = ffma2(a, wgo.y, ao[q]);
                    }
                }
            }

            // ===== L0 matmul (t+1): x(t+1) + h0(t) -> carried accums =====
            const float* xsrc;
            int lts;
            if (lt == CHUNK - 1) {
                asm volatile("cp.async.wait_group 0;");
                __syncwarp();
                xsrc = xs + (buf ^ 1) * 384;
                lts = 0;
            } else {
                xsrc = xs + buf * 384;
                lts = lt + 1;
            }
            #pragma unroll
            for (int q = 0; q < BPW; q++) {
                gai[q] = pk2(bi0, 0.f); gaf[q] = pk2(bf0, 0.f);
                gag[q] = pk2(bg0, 0.f); gao[q] = pk2(bo0, 0.f);
            }
            #pragma unroll
            for (int kp = 0; kp < 3; kp++) {
                #pragma unroll
                for (int q = 0; q < BPW; q++) {
                    unsigned long long a =
                        *(const unsigned long long*)(xsrc + q*96 + lts*6 + 2*kp);
                    gai[q] = ffma2(a, rIf[kp].x, gai[q]);
                    gaf[q] = ffma2(a, rIf[kp].y, gaf[q]);
                    gag[q] = ffma2(a, rGo[kp].x, gag[q]);
                    gao[q] = ffma2(a, rGo[kp].y, gao[q]);
                }
            }
            #pragma unroll
            for (int m = 0; m < 8; m++) {
                ulonglong2 h[BPW];
                #pragma unroll
                for (int q = 0; q < BPW; q++)
                    h[q] = ((const ulonglong2*)(h0wr + q*32))[m];
                #pragma unroll
                for (int s = 0; s < 2; s++) {
                    int kp = 2*m + s;
                    ulonglong2 wif = Whh0if[kp*32 + j];
                    ulonglong2 wgo = Whh0go[kp*32 + j];
                    #pragma unroll
                    for (int q = 0; q < BPW; q++) {
                        unsigned long long a = s ? h[q].y : h[q].x;
                        gai[q] = ffma2(a, wif.x, gai[q]);
                        gaf[q] = ffma2(a, wif.y, gaf[q]);
                        gag[q] = ffma2(a, wgo.x, gag[q]);
                        gao[q] = ffma2(a, wgo.y, gao[q]);
                    }
                }
            }

            // ===== L1 activations (t) -> store h1(t) =====
            #pragma unroll
            for (int q = 0; q < BPW; q++) {
                float2 ui = upk2(ai[q]), uf = upk2(af[q]);
                float2 ug = upk2(ag[q]), uo = upk2(ao[q]);
                float gi = sigap(ui.x + ui.y);
                float gf = sigap(uf.x + uf.y);
                float gg = tanhap(ug.x + ug.y);
                float go = sigap(uo.x + uo.y);
                c1[q] = gf * c1[q] + gi * gg;
                float hn = go * tanhap(c1[q]);
                h1wr[q*32 + j] = hn;
                h1last[q] = hn;
            }
            // next iteration's post-L0 syncwarp orders h1 stores
        }
        buf ^= 1;
    }

    // ===== final LayerNorm over H=32 =====
    float g = ln_gamma[j];
    float be = ln_beta[j];
    #pragma unroll
    for (int q = 0; q < BPW; q++) {
        if (b0 + q >= BATCH) break;
        float v = h1last[q];
        float s = v;
        #pragma unroll
        for (int o2 = 16; o2 > 0; o2 >>= 1) s += __shfl_xor_sync(0xffffffffu, s, o2);
        float mu = s * (1.0f / 32.0f);
        float dv = v - mu;
        float qq = dv * dv;
        #pragma unroll
        for (int o2 = 16; o2 > 0; o2 >>= 1) qq += __shfl_xor_sync(0xffffffffu, qq, o2);
        float var = qq * (1.0f / 32.0f);
        out[(size_t)(b0 + q) * 32 + j] = dv * rsqrtf(var + 1e-5f) * g + be;
    }
}

extern "C" void kernel_launch(void* const* d_in, const int* in_sizes, int n_in,
                              void* d_out, int out_size)
{
    const float* x      = (const float*)d_in[0];
    const float* W_ih0  = (const float*)d_in[1];
    const float* W_hh0  = (const float*)d_in[2];
    const float* b_ih0  = (const float*)d_in[3];
    const float* b_hh0  = (const float*)d_in[4];
    const float* W_ih1  = (const float*)d_in[5];
    const float* W_hh1  = (const float*)d_in[6];
    const float* b_ih1  = (const float*)d_in[7];
    const float* b_hh1  = (const float*)d_in[8];
    const float* ln_g   = (const float*)d_in[9];
    const float* ln_b   = (const float*)d_in[10];
    float* out = (float*)d_out;

    cudaFuncSetAttribute(lstm_enc_kernel,
                         cudaFuncAttributeMaxDynamicSharedMemorySize, SMEM_BYTES);
    lstm_enc_kernel<<<NUM_CTAS, CTA_THREADS, SMEM_BYTES>>>(
        x, W_ih0, W_hh0, b_ih0, b_hh0, W_ih1, W_hh1, b_ih1, b_hh1,
        ln_g, ln_b, out);
}

// round 14
// speedup vs baseline: 1.8474x; 1.6791x over previous
#include <cuda_runtime.h>
#include <cstdint>

// 2-layer LSTM (H=32) + LayerNorm. B=4096, T=512, D=6.
// Round 14: tf32 mma.sync.m16n8k8 tensor-core version.
// 128 CTAs x 256 thr. CTA = 32 batches. Warp owns 16 permuted gate-rows
// (R = 4*unit + gate). Weights = persistent A-fragments (tf32 hi+lo).
// h kept tf32 in shared, phys-interleaved so each B-fragment is one LDS.64.
// D transposed to (unit,batch) lanes by a 16-op shfl butterfly; c-state in
// registers. One __syncthreads per step. x staged via cp.async chunks.

#define T_STEPS 512
#define CHUNK 16
#define NCHUNK 32
#define NB 32
#define NUM_CTAS 128
#define THREADS 256

#define XS_STRIDE 100              // floats per batch row in x staging
#define XBUF_F (NB * XS_STRIDE)    // 3200
#define HS_STRIDE 40               // floats per batch row in h buffers
#define HBUF_F (NB * HS_STRIDE)    // 1280
#define SM_TOTAL (2 * XBUF_F + 4 * HBUF_F)   // 11520 floats = 46080 B

__device__ __forceinline__ uint32_t tf32c(float v) {
    uint32_t r;
    asm("cvt.rna.tf32.f32 %0, %1;" : "=r"(r) : "f"(v));
    return r;
}
__device__ __forceinline__ void mma8(float& d0, float& d1, float& d2, float& d3,
                                     uint32_t a0, uint32_t a1, uint32_t a2, uint32_t a3,
                                     uint32_t b0, uint32_t b1) {
    asm volatile(
        "mma.sync.aligned.m16n8k8.row.col.f32.tf32.tf32.f32 "
        "{%0,%1,%2,%3},{%4,%5,%6,%7},{%8,%9},{%0,%1,%2,%3};"
        : "+f"(d0), "+f"(d1), "+f"(d2), "+f"(d3)
        : "r"(a0), "r"(a1), "r"(a2), "r"(a3), "r"(b0), "r"(b1));
}
__device__ __forceinline__ float tanhap(float x) {
    float r;
    asm("tanh.approx.f32 %0, %1;" : "=f"(r) : "f"(x));
    return r;
}
__device__ __forceinline__ float sigap(float x) {
    return fmaf(0.5f, tanhap(0.5f * x), 0.5f);
}
__device__ __forceinline__ void cp_async16(uint32_t s, const void* g) {
    asm volatile("cp.async.ca.shared.global [%0], [%1], 16;" :: "r"(s), "l"(g));
}
// logical unit u -> phys slot: block(u>>3)*8 + ((u&3)<<1 | ((u>>2)&1))
__device__ __forceinline__ int physk(int u) {
    return ((u >> 3) << 3) | ((u & 3) << 1) | ((u >> 2) & 1);
}

__global__ __launch_bounds__(THREADS, 1)
void lstm_tc_kernel(const float* __restrict__ x,
                    const float* __restrict__ W_ih0,
                    const float* __restrict__ W_hh0,
                    const float* __restrict__ b_ih0,
                    const float* __restrict__ b_hh0,
                    const float* __restrict__ W_ih1,
                    const float* __restrict__ W_hh1,
                    const float* __restrict__ b_ih1,
                    const float* __restrict__ b_hh1,
                    const float* __restrict__ ln_gamma,
                    const float* __restrict__ ln_beta,
                    float* __restrict__ out)
{
    __shared__ float sm[SM_TOTAL];
    float* sm_x  = sm;                       // 2 x XBUF_F
    float* sm_h0 = sm + 2 * XBUF_F;          // 2 x HBUF_F
    float* sm_h1 = sm_h0 + 2 * HBUF_F;       // 2 x HBUF_F

    const int tid  = threadIdx.x;
    const int w    = tid >> 5;
    const int lane = tid & 31;
    const int c4 = lane & 3;                 // A k-col group / D col pair
    const int g8 = lane >> 2;                // A row group / B n-col
    const int p4 = g8 & 3;                   // gate this thread's rows carry

    const int R1 = 16 * w + g8;              // permuted row (unit U1, gate p4)
    const int U1 = R1 >> 2;
    const int U2 = U1 + 2;                   // row R1+8
    const int uC   = (p4 & 2) ? U2 : U1;     // combo owned after butterfly
    const int colC = 2 * c4 + (p4 & 1);
    const int physC = physk(uC);

    // zero both parities of h0 and h1
    for (int i = tid; i < 4 * HBUF_F; i += THREADS) sm_h0[i] = 0.0f;

    // ---- persistent A-fragments (weights), tf32 hi+lo ----
    // kt0 = W_ih0 (D=6 padded to 8); kt1..4 = W_hh0; kt5..8 = W_ih1; kt9..12 = W_hh1
    uint32_t A0h[13], A1h[13], A2h[13], A3h[13];
    uint32_t A0l[13], A1l[13], A2l[13], A3l[13];
    {
        const int row1 = p4 * 32 + U1;
        const int row2 = p4 * 32 + U2;
        #pragma unroll
        for (int kt = 0; kt < 13; kt++) {
            float v0, v1, v2, v3;
            if (kt == 0) {
                v0 = W_ih0[row1 * 6 + c4];
                v1 = W_ih0[row2 * 6 + c4];
                v2 = (c4 < 2) ? W_ih0[row1 * 6 + c4 + 4] : 0.0f;
                v3 = (c4 < 2) ? W_ih0[row2 * 6 + c4 + 4] : 0.0f;
            } else if (kt < 5) {
                int k = 8 * (kt - 1) + c4;
                v0 = W_hh0[row1 * 32 + k];     v1 = W_hh0[row2 * 32 + k];
                v2 = W_hh0[row1 * 32 + k + 4]; v3 = W_hh0[row2 * 32 + k + 4];
            } else if (kt < 9) {
                int k = 8 * (kt - 5) + c4;
                v0 = W_ih1[row1 * 32 + k];     v1 = W_ih1[row2 * 32 + k];
                v2 = W_ih1[row1 * 32 + k + 4]; v3 = W_ih1[row2 * 32 + k + 4];
            } else {
                int k = 8 * (kt - 9) + c4;
                v0 = W_hh1[row1 * 32 + k];     v1 = W_hh1[row2 * 32 + k];
                v2 = W_hh1[row1 * 32 + k + 4]; v3 = W_hh1[row2 * 32 + k + 4];
            }
            uint32_t h0b = tf32c(v0), h1b = tf32c(v1), h2b = tf32c(v2), h3b = tf32c(v3);
            A0h[kt] = h0b; A1h[kt] = h1b; A2h[kt] = h2b; A3h[kt] = h3b;
            A0l[kt] = tf32c(v0 - __uint_as_float(h0b));
            A1l[kt] = tf32c(v1 - __uint_as_float(h1b));
            A2l[kt] = tf32c(v2 - __uint_as_float(h2b));
            A3l[kt] = tf32c(v3 - __uint_as_float(h3b));
        }
    }

    const float bL0a = b_ih0[p4 * 32 + U1] + b_hh0[p4 * 32 + U1];
    const float bL0b = b_ih0[p4 * 32 + U2] + b_hh0[p4 * 32 + U2];
    const float bL1a = b_ih1[p4 * 32 + U1] + b_hh1[p4 * 32 + U1];
    const float bL1b = b_ih1[p4 * 32 + U2] + b_hh1[p4 * 32 + U2];

    const float* xg = x + (size_t)blockIdx.x * NB * (T_STEPS * 6);
    const uint32_t smx_u32 = (uint32_t)__cvta_generic_to_shared(sm_x);

    // prologue: stage chunk 0 into buffer 0 (768 float4 = 3 rounds of 256)
    {
        #pragma unroll
        for (int r = 0; r < 3; r++) {
            int fidx = tid + r * THREADS;
            int n = fidx / 24, f4 = fidx % 24;
            cp_async16(smx_u32 + (uint32_t)(n * XS_STRIDE + f4 * 4) * 4,
                       xg + (size_t)n * 3072 + f4 * 4);
        }
        asm volatile("cp.async.commit_group;");
        asm volatile("cp.async.wait_group 0;");
    }
    __syncthreads();

    float c0s[4] = {0, 0, 0, 0}, c1s[4] = {0, 0, 0, 0};

    int buf = 0;
    for (int tc = 0; tc < NCHUNK; tc++) {
        if (tc > 0) {
            asm volatile("cp.async.wait_group 0;");
            __syncthreads();
        }
        if (tc + 1 < NCHUNK) {
            uint32_t dst = smx_u32 + (uint32_t)((buf ^ 1) * XBUF_F) * 4;
            const int off = (tc + 1) * 96;
            #pragma unroll
            for (int r = 0; r < 3; r++) {
                int fidx = tid + r * THREADS;
                int n = fidx / 24, f4 = fidx % 24;
                cp_async16(dst + (uint32_t)(n * XS_STRIDE + f4 * 4) * 4,
                           xg + (size_t)n * 3072 + off + f4 * 4);
            }
            asm volatile("cp.async.commit_group;");
        }

        const float* cx = sm_x + buf * XBUF_F;

        #pragma unroll 1
        for (int lt = 0; lt < CHUNK; lt++) {
            const int t = tc * CHUNK + lt;
            const int p = t & 1;
            const float* h0r = sm_h0 + (p ^ 1) * HBUF_F;
            float*       h0w = sm_h0 + p * HBUF_F;
            const float* h1r = sm_h1 + (p ^ 1) * HBUF_F;
            float*       h1w = sm_h1 + p * HBUF_F;

            // ================= LAYER 0 =================
            float d0[4], d1[4], d2[4], d3[4];
            #pragma unroll
            for (int nt = 0; nt < 4; nt++) {
                d0[nt] = bL0a; d1[nt] = bL0a; d2[nt] = bL0b; d3[nt] = bL0b;
            }
            #pragma unroll
            for (int nt = 0; nt < 4; nt++) {      // kt0: x tile
                int n = g8 + 8 * nt;
                uint32_t b0 = tf32c(cx[n * XS_STRIDE + lt * 6 + c4]);
                uint32_t b1 = (c4 < 2) ? tf32c(cx[n * XS_STRIDE + lt * 6 + 4 + c4]) : 0u;
                mma8(d0[nt], d1[nt], d2[nt], d3[nt], A0h[0], A1h[0], A2h[0], A3h[0], b0, b1);
                mma8(d0[nt], d1[nt], d2[nt], d3[nt], A0l[0], A1l[0], A2l[0], A3l[0], b0, b1);
            }
            #pragma unroll
            for (int kt = 1; kt < 5; kt++) {      // h0(t-1)
                #pragma unroll
                for (int nt = 0; nt < 4; nt++) {
                    int n = g8 + 8 * nt;
                    uint2 bb = *(const uint2*)(h0r + n * HS_STRIDE + (kt - 1) * 8 + 2 * c4);
                    mma8(d0[nt], d1[nt], d2[nt], d3[nt], A0h[kt], A1h[kt], A2h[kt], A3h[kt], bb.x, bb.y);
                    mma8(d0[nt], d1[nt], d2[nt], d3[nt], A0l[kt], A1l[kt], A2l[kt], A3l[kt], bb.x, bb.y);
                }
            }
            #pragma unroll
            for (int nt = 0; nt < 4; nt++) {      // butterfly + act + store h0
                float D0 = d0[nt], D1 = d1[nt], D2 = d2[nt], D3 = d3[nt];
                float sa = (p4 & 1) ? D0 : D1; float ra = __shfl_xor_sync(0xffffffffu, sa, 4);
                float sb = (p4 & 1) ? D2 : D3; float rb = __shfl_xor_sync(0xffffffffu, sb, 4);
                float e0 = (p4 & 1) ? ra : D0;
                float e1 = (p4 & 1) ? D1 : ra;
                float e2 = (p4 & 1) ? rb : D2;
                float e3 = (p4 & 1) ? D3 : rb;
                float sc = (p4 & 2) ? e0 : e2; float rc = __shfl_xor_sync(0xffffffffu, sc, 8);
                float sd = (p4 & 2) ? e1 : e3; float rd = __shfl_xor_sync(0xffffffffu, sd, 8);
                float F0 = (p4 & 2) ? rc : e0;
                float F2 = (p4 & 2) ? e2 : rc;
                float F1 = (p4 & 2) ? rd : e1;
                float F3 = (p4 & 2) ? e3 : rd;
                float gi = sigap(F0), gf = sigap(F1), gg = tanhap(F2), go = sigap(F3);
                c0s[nt] = gf * c0s[nt] + gi * gg;
                float hv = go * tanhap(c0s[nt]);
                *(uint32_t*)(h0w + (8 * nt + colC) * HS_STRIDE + physC) = tf32c(hv);
            }
            __syncthreads();   // single per-step barrier

            // ================= LAYER 1 =================
            #pragma unroll
            for (int nt = 0; nt < 4; nt++) {
                d0[nt] = bL1a; d1[nt] = bL1a; d2[nt] = bL1b; d3[nt] = bL1b;
            }
            #pragma unroll
            for (int kt = 0; kt < 4; kt++) {      // h0(t)
                #pragma unroll
                for (int nt = 0; nt < 4; nt++) {
                    int n = g8 + 8 * nt;
                    uint2 bb = *(const uint2*)(h0w + n * HS_STRIDE + kt * 8 + 2 * c4);
                    mma8(d0[nt], d1[nt], d2[nt], d3[nt],
                         A0h[5 + kt], A1h[5 + kt], A2h[5 + kt], A3h[5 + kt], bb.x, bb.y);
                    mma8(d0[nt], d1[nt], d2[nt], d3[nt],
                         A0l[5 + kt], A1l[5 + kt], A2l[5 + kt], A3l[5 + kt], bb.x, bb.y);
                }
            }
            #pragma unroll
            for (int kt = 0; kt < 4; kt++) {      // h1(t-1)
                #pragma unroll
                for (int nt = 0; nt < 4; nt++) {
                    int n = g8 + 8 * nt;
                    uint2 bb = *(const uint2*)(h1r + n * HS_STRIDE + kt * 8 + 2 * c4);
                    mma8(d0[nt], d1[nt], d2[nt], d3[nt],
                         A0h[9 + kt], A1h[9 + kt], A2h[9 + kt], A3h[9 + kt], bb.x, bb.y);
                    mma8(d0[nt], d1[nt], d2[nt], d3[nt],
                         A0l[9 + kt], A1l[9 + kt], A2l[9 + kt], A3l[9 + kt], bb.x, bb.y);
                }
            }
            #pragma unroll
            for (int nt = 0; nt < 4; nt++) {      // butterfly + act + store h1
                float D0 = d0[nt], D1 = d1[nt], D2 = d2[nt], D3 = d3[nt];
                float sa = (p4 & 1) ? D0 : D1; float ra = __shfl_xor_sync(0xffffffffu, sa, 4);
                float sb = (p4 & 1) ? D2 : D3; float rb = __shfl_xor_sync(0xffffffffu, sb, 4);
                float e0 = (p4 & 1) ? ra : D0;
                float e1 = (p4 & 1) ? D1 : ra;
                float e2 = (p4 & 1) ? rb : D2;
                float e3 = (p4 & 1) ? D3 : rb;
                float sc = (p4 & 2) ? e0 : e2; float rc = __shfl_xor_sync(0xffffffffu, sc, 8);
                float sd = (p4 & 2) ? e1 : e3; float rd = __shfl_xor_sync(0xffffffffu, sd, 8);
                float F0 = (p4 & 2) ? rc : e0;
                float F2 = (p4 & 2) ? e2 : rc;
                float F1 = (p4 & 2) ? rd : e1;
                float F3 = (p4 & 2) ? e3 : rd;
                float gi = sigap(F0), gf = sigap(F1), gg = tanhap(F2), go = sigap(F3);
                c1s[nt] = gf * c1s[nt] + gi * gg;
                float hv = go * tanhap(c1s[nt]);
                *(uint32_t*)(h1w + (8 * nt + colC) * HS_STRIDE + physC) = tf32c(hv);
                if (t == T_STEPS - 1) {
                    // f32 h1 for LayerNorm into idle x buffer 0 (stride 33)
                    sm_x[(8 * nt + colC) * 33 + uC] = hv;
                }
            }
            // next step's post-L0 barrier orders h1 stores
        }
        buf ^= 1;
    }

    // ================= final LayerNorm over H=32 =================
    __syncthreads();
    {
        const float* hf = sm_x;   // [batch][33] f32
        float gam = ln_gamma[lane];
        float bet = ln_beta[lane];
        #pragma unroll
        for (int nb = 0; nb < 4; nb++) {
            int n = 4 * w + nb;
            float v = hf[n * 33 + lane];
            float s = v;
            #pragma unroll
            for (int o2 = 16; o2 > 0; o2 >>= 1) s += __shfl_xor_sync(0xffffffffu, s, o2);
            float mu = s * (1.0f / 32.0f);
            float dv = v - mu;
            float qq = dv * dv;
            #pragma unroll
            for (int o2 = 16; o2 > 0; o2 >>= 1) qq += __shfl_xor_sync(0xffffffffu, qq, o2);
            float var = qq * (1.0f / 32.0f);
            out[((size_t)blockIdx.x * NB + n) * 32 + lane] =
                dv * rsqrtf(var + 1e-5f) * gam + bet;
        }
    }
}

extern "C" void kernel_launch(void* const* d_in, const int* in_sizes, int n_in,
                              void* d_out, int out_size)
{
    const float* x      = (const float*)d_in[0];
    const float* W_ih0  = (const float*)d_in[1];
    const float* W_hh0  = (const float*)d_in[2];
    const float* b_ih0  = (const float*)d_in[3];
    const float* b_hh0  = (const float*)d_in[4];
    const float* W_ih1  = (const float*)d_in[5];
    const float* W_hh1  = (const float*)d_in[6];
    const float* b_ih1  = (const float*)d_in[7];
    const float* b_hh1  = (const float*)d_in[8];
    const float* ln_g   = (const float*)d_in[9];
    const float* ln_b   = (const float*)d_in[10];
    float* out = (float*)d_out;

    lstm_tc_kernel<<<NUM_CTAS, THREADS>>>(
        x, W_ih0, W_hh0, b_ih0, b_hh0, W_ih1, W_hh1, b_ih1, b_hh1,
        ln_g, ln_b, out);
}

// round 15
// speedup vs baseline: 2.0155x; 1.0910x over previous
#include <cuda_runtime.h>
#include <cstdint>

// 2-layer LSTM (H=32) + LayerNorm. B=4096, T=512, D=6.
// Round 15: tf32 mma tensor-core version + cross-layer pipeline.
// Step order: L0-act(t)[carried accums] -> store h0 -> sync ->
//             {L1-mm(t) || L0-mm(t+1)} -> L1-act(t) -> store h1.
// 128 CTAs x 256 thr; warp owns 16 permuted gate-rows (R=4*unit+gate);
// weights persistent in A-fragments (tf32 hi+lo); h tf32 in shared,
// phys-interleaved (B-frag = one LDS.64); D via 16-op shfl butterfly.

#define T_STEPS 512
#define CHUNK 16
#define NCHUNK 32
#define NB 32
#define NUM_CTAS 128
#define THREADS 256

#define XS_STRIDE 100
#define XBUF_F (NB * XS_STRIDE)
#define HS_STRIDE 40
#define HBUF_F (NB * HS_STRIDE)
#define SM_TOTAL (2 * XBUF_F + 4 * HBUF_F)

__device__ __forceinline__ uint32_t tf32c(float v) {
    uint32_t r;
    asm("cvt.rna.tf32.f32 %0, %1;" : "=r"(r) : "f"(v));
    return r;
}
__device__ __forceinline__ void mma8(float& d0, float& d1, float& d2, float& d3,
                                     uint32_t a0, uint32_t a1, uint32_t a2, uint32_t a3,
                                     uint32_t b0, uint32_t b1) {
    asm volatile(
        "mma.sync.aligned.m16n8k8.row.col.f32.tf32.tf32.f32 "
        "{%0,%1,%2,%3},{%4,%5,%6,%7},{%8,%9},{%0,%1,%2,%3};"
        : "+f"(d0), "+f"(d1), "+f"(d2), "+f"(d3)
        : "r"(a0), "r"(a1), "r"(a2), "r"(a3), "r"(b0), "r"(b1));
}
__device__ __forceinline__ float tanhap(float x) {
    float r;
    asm("tanh.approx.f32 %0, %1;" : "=f"(r) : "f"(x));
    return r;
}
__device__ __forceinline__ float sigap(float x) {
    return fmaf(0.5f, tanhap(0.5f * x), 0.5f);
}
__device__ __forceinline__ void cp_async16(uint32_t s, const void* g) {
    asm volatile("cp.async.ca.shared.global [%0], [%1], 16;" :: "r"(s), "l"(g));
}
__device__ __forceinline__ int physk(int u) {
    return ((u >> 3) << 3) | ((u & 3) << 1) | ((u >> 2) & 1);
}
// butterfly transpose of one D-fragment group + LSTM cell update
__device__ __forceinline__ float act_combo(float D0, float D1, float D2, float D3,
                                           int p4, float& c) {
    float sa = (p4 & 1) ? D0 : D1; float ra = __shfl_xor_sync(0xffffffffu, sa, 4);
    float sb = (p4 & 1) ? D2 : D3; float rb = __shfl_xor_sync(0xffffffffu, sb, 4);
    float e0 = (p4 & 1) ? ra : D0;
    float e1 = (p4 & 1) ? D1 : ra;
    float e2 = (p4 & 1) ? rb : D2;
    float e3 = (p4 & 1) ? D3 : rb;
    float sc = (p4 & 2) ? e0 : e2; float rc = __shfl_xor_sync(0xffffffffu, sc, 8);
    float sd = (p4 & 2) ? e1 : e3; float rd = __shfl_xor_sync(0xffffffffu, sd, 8);
    float F0 = (p4 & 2) ? rc : e0;
    float F2 = (p4 & 2) ? e2 : rc;
    float F1 = (p4 & 2) ? rd : e1;
    float F3 = (p4 & 2) ? e3 : rd;
    float gi = sigap(F0), gf = sigap(F1), gg = tanhap(F2), go = sigap(F3);
    c = gf * c + gi * gg;
    return go * tanhap(c);
}

__global__ __launch_bounds__(THREADS, 1)
void lstm_tc_kernel(const float* __restrict__ x,
                    const float* __restrict__ W_ih0,
                    const float* __restrict__ W_hh0,
                    const float* __restrict__ b_ih0,
                    const float* __restrict__ b_hh0,
                    const float* __restrict__ W_ih1,
                    const float* __restrict__ W_hh1,
                    const float* __restrict__ b_ih1,
                    const float* __restrict__ b_hh1,
                    const float* __restrict__ ln_gamma,
                    const float* __restrict__ ln_beta,
                    float* __restrict__ out)
{
    __shared__ float sm[SM_TOTAL];
    float* sm_x  = sm;
    float* sm_h0 = sm + 2 * XBUF_F;
    float* sm_h1 = sm_h0 + 2 * HBUF_F;

    const int tid  = threadIdx.x;
    const int w    = tid >> 5;
    const int lane = tid & 31;
    const int c4 = lane & 3;
    const int g8 = lane >> 2;
    const int p4 = g8 & 3;

    const int R1 = 16 * w + g8;
    const int U1 = R1 >> 2;
    const int U2 = U1 + 2;
    const int uC   = (p4 & 2) ? U2 : U1;
    const int colC = 2 * c4 + (p4 & 1);
    const int physC = physk(uC);

    for (int i = tid; i < 4 * HBUF_F; i += THREADS) sm_h0[i] = 0.0f;

    // ---- persistent A-fragments (tf32 hi+lo) ----
    uint32_t A0h[13], A1h[13], A2h[13], A3h[13];
    uint32_t A0l[13], A1l[13], A2l[13], A3l[13];
    {
        const int row1 = p4 * 32 + U1;
        const int row2 = p4 * 32 + U2;
        #pragma unroll
        for (int kt = 0; kt < 13; kt++) {
            float v0, v1, v2, v3;
            if (kt == 0) {
                v0 = W_ih0[row1 * 6 + c4];
                v1 = W_ih0[row2 * 6 + c4];
                v2 = (c4 < 2) ? W_ih0[row1 * 6 + c4 + 4] : 0.0f;
                v3 = (c4 < 2) ? W_ih0[row2 * 6 + c4 + 4] : 0.0f;
            } else if (kt < 5) {
                int k = 8 * (kt - 1) + c4;
                v0 = W_hh0[row1 * 32 + k];     v1 = W_hh0[row2 * 32 + k];
                v2 = W_hh0[row1 * 32 + k + 4]; v3 = W_hh0[row2 * 32 + k + 4];
            } else if (kt < 9) {
                int k = 8 * (kt - 5) + c4;
                v0 = W_ih1[row1 * 32 + k];     v1 = W_ih1[row2 * 32 + k];
                v2 = W_ih1[row1 * 32 + k + 4]; v3 = W_ih1[row2 * 32 + k + 4];
            } else {
                int k = 8 * (kt - 9) + c4;
                v0 = W_hh1[row1 * 32 + k];     v1 = W_hh1[row2 * 32 + k];
                v2 = W_hh1[row1 * 32 + k + 4]; v3 = W_hh1[row2 * 32 + k + 4];
            }
            uint32_t h0b = tf32c(v0), h1b = tf32c(v1), h2b = tf32c(v2), h3b = tf32c(v3);
            A0h[kt] = h0b; A1h[kt] = h1b; A2h[kt] = h2b; A3h[kt] = h3b;
            A0l[kt] = tf32c(v0 - __uint_as_float(h0b));
            A1l[kt] = tf32c(v1 - __uint_as_float(h1b));
            A2l[kt] = tf32c(v2 - __uint_as_float(h2b));
            A3l[kt] = tf32c(v3 - __uint_as_float(h3b));
        }
    }

    const float bL0a = b_ih0[p4 * 32 + U1] + b_hh0[p4 * 32 + U1];
    const float bL0b = b_ih0[p4 * 32 + U2] + b_hh0[p4 * 32 + U2];
    const float bL1a = b_ih1[p4 * 32 + U1] + b_hh1[p4 * 32 + U1];
    const float bL1b = b_ih1[p4 * 32 + U2] + b_hh1[p4 * 32 + U2];

    const float* xg = x + (size_t)blockIdx.x * NB * (T_STEPS * 6);
    const uint32_t smx_u32 = (uint32_t)__cvta_generic_to_shared(sm_x);

    // prologue: stage chunk 0 into buffer 0
    {
        #pragma unroll
        for (int r = 0; r < 3; r++) {
            int fidx = tid + r * THREADS;
            int n = fidx / 24, f4 = fidx % 24;
            cp_async16(smx_u32 + (uint32_t)(n * XS_STRIDE + f4 * 4) * 4,
                       xg + (size_t)n * 3072 + f4 * 4);
        }
        asm volatile("cp.async.commit_group;");
        asm volatile("cp.async.wait_group 0;");
    }
    __syncthreads();

    float c0s[4] = {0, 0, 0, 0}, c1s[4] = {0, 0, 0, 0};

    // carried L0 accums for t=0: bias + W_ih0 x(0)  (h0(-1)=0)
    float g0[4], g1[4], g2[4], g3[4];
    #pragma unroll
    for (int nt = 0; nt < 4; nt++) { g0[nt] = bL0a; g1[nt] = bL0a; g2[nt] = bL0b; g3[nt] = bL0b; }
    #pragma unroll
    for (int nt = 0; nt < 4; nt++) {
        int n = g8 + 8 * nt;
        uint32_t b0 = tf32c(sm_x[n * XS_STRIDE + c4]);
        uint32_t b1 = (c4 < 2) ? tf32c(sm_x[n * XS_STRIDE + 4 + c4]) : 0u;
        mma8(g0[nt], g1[nt], g2[nt], g3[nt], A0h[0], A1h[0], A2h[0], A3h[0], b0, b1);
        mma8(g0[nt], g1[nt], g2[nt], g3[nt], A0l[0], A1l[0], A2l[0], A3l[0], b0, b1);
    }

    for (int tc = 0; tc < NCHUNK; tc++) {
        const int b = tc & 1;
        const float* cx = sm_x + b * XBUF_F;

        if (tc + 1 < NCHUNK) {
            uint32_t dst = smx_u32 + (uint32_t)((b ^ 1) * XBUF_F) * 4;
            const int off = (tc + 1) * 96;
            #pragma unroll
            for (int r = 0; r < 3; r++) {
                int fidx = tid + r * THREADS;
                int n = fidx / 24, f4 = fidx % 24;
                cp_async16(dst + (uint32_t)(n * XS_STRIDE + f4 * 4) * 4,
                           xg + (size_t)n * 3072 + off + f4 * 4);
            }
            asm volatile("cp.async.commit_group;");
        }

        #pragma unroll 1
        for (int lt = 0; lt < CHUNK; lt++) {
            const int t = tc * CHUNK + lt;
            const int p = t & 1;
            float*       h0w = sm_h0 + p * HBUF_F;
            const float* h1r = sm_h1 + (p ^ 1) * HBUF_F;
            float*       h1w = sm_h1 + p * HBUF_F;

            // ===== L0 activations (from carried accums) -> store h0(t) =====
            #pragma unroll
            for (int nt = 0; nt < 4; nt++) {
                float hv = act_combo(g0[nt], g1[nt], g2[nt], g3[nt], p4, c0s[nt]);
                *(uint32_t*)(h0w + (8 * nt + colC) * HS_STRIDE + physC) = tf32c(hv);
            }
            __syncthreads();   // the per-step barrier

            // ===== L1-mm(t) =====
            float d0[4], d1[4], d2[4], d3[4];
            #pragma unroll
            for (int nt = 0; nt < 4; nt++) {
                d0[nt] = bL1a; d1[nt] = bL1a; d2[nt] = bL1b; d3[nt] = bL1b;
            }
            #pragma unroll
            for (int kt = 0; kt < 4; kt++) {        // h0(t)
                #pragma unroll
                for (int nt = 0; nt < 4; nt++) {
                    int n = g8 + 8 * nt;
                    uint2 bb = *(const uint2*)(h0w + n * HS_STRIDE + kt * 8 + 2 * c4);
                    mma8(d0[nt], d1[nt], d2[nt], d3[nt],
                         A0h[5 + kt], A1h[5 + kt], A2h[5 + kt], A3h[5 + kt], bb.x, bb.y);
                    mma8(d0[nt], d1[nt], d2[nt], d3[nt],
                         A0l[5 + kt], A1l[5 + kt], A2l[5 + kt], A3l[5 + kt], bb.x, bb.y);
                }
            }
            #pragma unroll
            for (int kt = 0; kt < 4; kt++) {        // h1(t-1)
                #pragma unroll
                for (int nt = 0; nt < 4; nt++) {
                    int n = g8 + 8 * nt;
                    uint2 bb = *(const uint2*)(h1r + n * HS_STRIDE + kt * 8 + 2 * c4);
                    mma8(d0[nt], d1[nt], d2[nt], d3[nt],
                         A0h[9 + kt], A1h[9 + kt], A2h[9 + kt], A3h[9 + kt], bb.x, bb.y);
                    mma8(d0[nt], d1[nt], d2[nt], d3[nt],
                         A0l[9 + kt], A1l[9 + kt], A2l[9 + kt], A3l[9 + kt], bb.x, bb.y);
                }
            }

            // ===== L0-mm(t+1): bias + W_ih0 x(t+1) + W_hh0 h0(t) =====
            const float* xsrc;
            int lts;
            if (lt == CHUNK - 1) {
                if (tc + 1 < NCHUNK) {
                    asm volatile("cp.async.wait_group 0;");
                    __syncthreads();
                    xsrc = sm_x + (b ^ 1) * XBUF_F;
                    lts = 0;
                } else {                      // t=511: result unused, clamp
                    xsrc = cx; lts = CHUNK - 1;
                }
            } else {
                xsrc = cx; lts = lt + 1;
            }
            #pragma unroll
            for (int nt = 0; nt < 4; nt++) {
                g0[nt] = bL0a; g1[nt] = bL0a; g2[nt] = bL0b; g3[nt] = bL0b;
            }
            #pragma unroll
            for (int nt = 0; nt < 4; nt++) {        // x(t+1)
                int n = g8 + 8 * nt;
                uint32_t b0 = tf32c(xsrc[n * XS_STRIDE + lts * 6 + c4]);
                uint32_t b1 = (c4 < 2) ? tf32c(xsrc[n * XS_STRIDE + lts * 6 + 4 + c4]) : 0u;
                mma8(g0[nt], g1[nt], g2[nt], g3[nt], A0h[0], A1h[0], A2h[0], A3h[0], b0, b1);
                mma8(g0[nt], g1[nt], g2[nt], g3[nt], A0l[0], A1l[0], A2l[0], A3l[0], b0, b1);
            }
            #pragma unroll
            for (int kt = 1; kt < 5; kt++) {        // h0(t)
                #pragma unroll
                for (int nt = 0; nt < 4; nt++) {
                    int n = g8 + 8 * nt;
                    uint2 bb = *(const uint2*)(h0w + n * HS_STRIDE + (kt - 1) * 8 + 2 * c4);
                    mma8(g0[nt], g1[nt], g2[nt], g3[nt], A0h[kt], A1h[kt], A2h[kt], A3h[kt], bb.x, bb.y);
                    mma8(g0[nt], g1[nt], g2[nt], g3[nt], A0l[kt], A1l[kt], A2l[kt], A3l[kt], bb.x, bb.y);
                }
            }

            // ===== L1 activations (t) -> store h1(t) =====
            #pragma unroll
            for (int nt = 0; nt < 4; nt++) {
                float hv = act_combo(d0[nt], d1[nt], d2[nt], d3[nt], p4, c1s[nt]);
                *(uint32_t*)(h1w + (8 * nt + colC) * HS_STRIDE + physC) = tf32c(hv);
                if (t == T_STEPS - 1)
                    sm_x[(8 * nt + colC) * 33 + uC] = hv;   // f32 for LayerNorm
            }
            // next step's post-L0 barrier orders h1 stores
        }
    }

    // ================= final LayerNorm over H=32 =================
    __syncthreads();
    {
        const float* hf = sm_x;   // [batch][33] f32
        float gam = ln_gamma[lane];
        float bet = ln_beta[lane];
        #pragma unroll
        for (int nb = 0; nb < 4; nb++) {
            int n = 4 * w + nb;
            float v = hf[n * 33 + lane];
            float s = v;
            #pragma unroll
            for (int o2 = 16; o2 > 0; o2 >>= 1) s += __shfl_xor_sync(0xffffffffu, s, o2);
            float mu = s * (1.0f / 32.0f);
            float dv = v - mu;
            float qq = dv * dv;
            #pragma unroll
            for (int o2 = 16; o2 > 0; o2 >>= 1) qq += __shfl_xor_sync(0xffffffffu, qq, o2);
            float var = qq * (1.0f / 32.0f);
            out[((size_t)blockIdx.x * NB + n) * 32 + lane] =
                dv * rsqrtf(var + 1e-5f) * gam + bet;
        }
    }
}

extern "C" void kernel_launch(void* const* d_in, const int* in_sizes, int n_in,
                              void* d_out, int out_size)
{
    const float* x      = (const float*)d_in[0];
    const float* W_ih0  = (const float*)d_in[1];
    const float* W_hh0  = (const float*)d_in[2];
    const float* b_ih0  = (const float*)d_in[3];
    const float* b_hh0  = (const float*)d_in[4];
    const float* W_ih1  = (const float*)d_in[5];
    const float* W_hh1  = (const float*)d_in[6];
    const float* b_ih1  = (const float*)d_in[7];
    const float* b_hh1  = (const float*)d_in[8];
    const float* ln_g   = (const float*)d_in[9];
    const float* ln_b   = (const float*)d_in[10];
    float* out = (float*)d_out;

    lstm_tc_kernel<<<NUM_CTAS, THREADS>>>(
        x, W_ih0, W_hh0, b_ih0, b_hh0, W_ih1, W_hh1, b_ih1, b_hh1,
        ln_g, ln_b, out);
}

// round 16
// speedup vs baseline: 2.5984x; 1.2892x over previous
#include <cuda_runtime.h>
#include <cstdint>

// 2-layer LSTM (H=32) + LayerNorm. B=4096, T=512, D=6.
// Round 16: R15 pipeline + hi-only tf32 weights (52 mma/warp-step, was 104).
// Rationale: h is already tf32-rounded per step and final rel_err is 5.8e-5;
// tf32 weight rounding adds same-order error -> est 1-2e-4, inside 1e-3.
// Step: L0-act(t)[carried] -> store h0 -> sync -> {L1-mm(t) || L0-mm(t+1)}
//       -> L1-act(t) -> store h1.

#define T_STEPS 512
#define CHUNK 16
#define NCHUNK 32
#define NB 32
#define NUM_CTAS 128
#define THREADS 256

#define XS_STRIDE 100
#define XBUF_F (NB * XS_STRIDE)
#define HS_STRIDE 40
#define HBUF_F (NB * HS_STRIDE)
#define SM_TOTAL (2 * XBUF_F + 4 * HBUF_F)

__device__ __forceinline__ uint32_t tf32c(float v) {
    uint32_t r;
    asm("cvt.rna.tf32.f32 %0, %1;" : "=r"(r) : "f"(v));
    return r;
}
__device__ __forceinline__ void mma8(float& d0, float& d1, float& d2, float& d3,
                                     uint32_t a0, uint32_t a1, uint32_t a2, uint32_t a3,
                                     uint32_t b0, uint32_t b1) {
    asm volatile(
        "mma.sync.aligned.m16n8k8.row.col.f32.tf32.tf32.f32 "
        "{%0,%1,%2,%3},{%4,%5,%6,%7},{%8,%9},{%0,%1,%2,%3};"
        : "+f"(d0), "+f"(d1), "+f"(d2), "+f"(d3)
        : "r"(a0), "r"(a1), "r"(a2), "r"(a3), "r"(b0), "r"(b1));
}
__device__ __forceinline__ float tanhap(float x) {
    float r;
    asm("tanh.approx.f32 %0, %1;" : "=f"(r) : "f"(x));
    return r;
}
__device__ __forceinline__ float sigap(float x) {
    return fmaf(0.5f, tanhap(0.5f * x), 0.5f);
}
__device__ __forceinline__ void cp_async16(uint32_t s, const void* g) {
    asm volatile("cp.async.ca.shared.global [%0], [%1], 16;" :: "r"(s), "l"(g));
}
__device__ __forceinline__ int physk(int u) {
    return ((u >> 3) << 3) | ((u & 3) << 1) | ((u >> 2) & 1);
}
// butterfly transpose of one D-fragment group + LSTM cell update
__device__ __forceinline__ float act_combo(float D0, float D1, float D2, float D3,
                                           int p4, float& c) {
    float sa = (p4 & 1) ? D0 : D1; float ra = __shfl_xor_sync(0xffffffffu, sa, 4);
    float sb = (p4 & 1) ? D2 : D3; float rb = __shfl_xor_sync(0xffffffffu, sb, 4);
    float e0 = (p4 & 1) ? ra : D0;
    float e1 = (p4 & 1) ? D1 : ra;
    float e2 = (p4 & 1) ? rb : D2;
    float e3 = (p4 & 1) ? D3 : rb;
    float sc = (p4 & 2) ? e0 : e2; float rc = __shfl_xor_sync(0xffffffffu, sc, 8);
    float sd = (p4 & 2) ? e1 : e3; float rd = __shfl_xor_sync(0xffffffffu, sd, 8);
    float F0 = (p4 & 2) ? rc : e0;
    float F2 = (p4 & 2) ? e2 : rc;
    float F1 = (p4 & 2) ? rd : e1;
    float F3 = (p4 & 2) ? e3 : rd;
    float gi = sigap(F0), gf = sigap(F1), gg = tanhap(F2), go = sigap(F3);
    c = gf * c + gi * gg;
    return go * tanhap(c);
}

__global__ __launch_bounds__(THREADS, 1)
void lstm_tc_kernel(const float* __restrict__ x,
                    const float* __restrict__ W_ih0,
                    const float* __restrict__ W_hh0,
                    const float* __restrict__ b_ih0,
                    const float* __restrict__ b_hh0,
                    const float* __restrict__ W_ih1,
                    const float* __restrict__ W_hh1,
                    const float* __restrict__ b_ih1,
                    const float* __restrict__ b_hh1,
                    const float* __restrict__ ln_gamma,
                    const float* __restrict__ ln_beta,
                    float* __restrict__ out)
{
    __shared__ float sm[SM_TOTAL];
    float* sm_x  = sm;
    float* sm_h0 = sm + 2 * XBUF_F;
    float* sm_h1 = sm_h0 + 2 * HBUF_F;

    const int tid  = threadIdx.x;
    const int w    = tid >> 5;
    const int lane = tid & 31;
    const int c4 = lane & 3;
    const int g8 = lane >> 2;
    const int p4 = g8 & 3;

    const int R1 = 16 * w + g8;
    const int U1 = R1 >> 2;
    const int U2 = U1 + 2;
    const int uC   = (p4 & 2) ? U2 : U1;
    const int colC = 2 * c4 + (p4 & 1);
    const int physC = physk(uC);

    for (int i = tid; i < 4 * HBUF_F; i += THREADS) sm_h0[i] = 0.0f;

    // ---- persistent A-fragments (tf32, hi only) ----
    uint32_t A0[13], A1[13], A2[13], A3[13];
    {
        const int row1 = p4 * 32 + U1;
        const int row2 = p4 * 32 + U2;
        #pragma unroll
        for (int kt = 0; kt < 13; kt++) {
            float v0, v1, v2, v3;
            if (kt == 0) {
                v0 = W_ih0[row1 * 6 + c4];
                v1 = W_ih0[row2 * 6 + c4];
                v2 = (c4 < 2) ? W_ih0[row1 * 6 + c4 + 4] : 0.0f;
                v3 = (c4 < 2) ? W_ih0[row2 * 6 + c4 + 4] : 0.0f;
            } else if (kt < 5) {
                int k = 8 * (kt - 1) + c4;
                v0 = W_hh0[row1 * 32 + k];     v1 = W_hh0[row2 * 32 + k];
                v2 = W_hh0[row1 * 32 + k + 4]; v3 = W_hh0[row2 * 32 + k + 4];
            } else if (kt < 9) {
                int k = 8 * (kt - 5) + c4;
                v0 = W_ih1[row1 * 32 + k];     v1 = W_ih1[row2 * 32 + k];
                v2 = W_ih1[row1 * 32 + k + 4]; v3 = W_ih1[row2 * 32 + k + 4];
            } else {
                int k = 8 * (kt - 9) + c4;
                v0 = W_hh1[row1 * 32 + k];     v1 = W_hh1[row2 * 32 + k];
                v2 = W_hh1[row1 * 32 + k + 4]; v3 = W_hh1[row2 * 32 + k + 4];
            }
            A0[kt] = tf32c(v0); A1[kt] = tf32c(v1);
            A2[kt] = tf32c(v2); A3[kt] = tf32c(v3);
        }
    }

    const float bL0a = b_ih0[p4 * 32 + U1] + b_hh0[p4 * 32 + U1];
    const float bL0b = b_ih0[p4 * 32 + U2] + b_hh0[p4 * 32 + U2];
    const float bL1a = b_ih1[p4 * 32 + U1] + b_hh1[p4 * 32 + U1];
    const float bL1b = b_ih1[p4 * 32 + U2] + b_hh1[p4 * 32 + U2];

    const float* xg = x + (size_t)blockIdx.x * NB * (T_STEPS * 6);
    const uint32_t smx_u32 = (uint32_t)__cvta_generic_to_shared(sm_x);

    // prologue: stage chunk 0 into buffer 0
    {
        #pragma unroll
        for (int r = 0; r < 3; r++) {
            int fidx = tid + r * THREADS;
            int n = fidx / 24, f4 = fidx % 24;
            cp_async16(smx_u32 + (uint32_t)(n * XS_STRIDE + f4 * 4) * 4,
                       xg + (size_t)n * 3072 + f4 * 4);
        }
        asm volatile("cp.async.commit_group;");
        asm volatile("cp.async.wait_group 0;");
    }
    __syncthreads();

    float c0s[4] = {0, 0, 0, 0}, c1s[4] = {0, 0, 0, 0};

    // carried L0 accums for t=0: bias + W_ih0 x(0)
    float g0[4], g1[4], g2[4], g3[4];
    #pragma unroll
    for (int nt = 0; nt < 4; nt++) { g0[nt] = bL0a; g1[nt] = bL0a; g2[nt] = bL0b; g3[nt] = bL0b; }
    #pragma unroll
    for (int nt = 0; nt < 4; nt++) {
        int n = g8 + 8 * nt;
        uint32_t b0 = tf32c(sm_x[n * XS_STRIDE + c4]);
        uint32_t b1 = (c4 < 2) ? tf32c(sm_x[n * XS_STRIDE + 4 + c4]) : 0u;
        mma8(g0[nt], g1[nt], g2[nt], g3[nt], A0[0], A1[0], A2[0], A3[0], b0, b1);
    }

    for (int tc = 0; tc < NCHUNK; tc++) {
        const int b = tc & 1;
        const float* cx = sm_x + b * XBUF_F;

        if (tc + 1 < NCHUNK) {
            uint32_t dst = smx_u32 + (uint32_t)((b ^ 1) * XBUF_F) * 4;
            const int off = (tc + 1) * 96;
            #pragma unroll
            for (int r = 0; r < 3; r++) {
                int fidx = tid + r * THREADS;
                int n = fidx / 24, f4 = fidx % 24;
                cp_async16(dst + (uint32_t)(n * XS_STRIDE + f4 * 4) * 4,
                           xg + (size_t)n * 3072 + off + f4 * 4);
            }
            asm volatile("cp.async.commit_group;");
        }

        #pragma unroll 1
        for (int lt = 0; lt < CHUNK; lt++) {
            const int t = tc * CHUNK + lt;
            const int p = t & 1;
            float*       h0w = sm_h0 + p * HBUF_F;
            const float* h1r = sm_h1 + (p ^ 1) * HBUF_F;
            float*       h1w = sm_h1 + p * HBUF_F;

            // ===== L0 activations (carried accums) -> store h0(t) =====
            #pragma unroll
            for (int nt = 0; nt < 4; nt++) {
                float hv = act_combo(g0[nt], g1[nt], g2[nt], g3[nt], p4, c0s[nt]);
                *(uint32_t*)(h0w + (8 * nt + colC) * HS_STRIDE + physC) = tf32c(hv);
            }
            __syncthreads();

            // ===== L1-mm(t) =====
            float d0[4], d1[4], d2[4], d3[4];
            #pragma unroll
            for (int nt = 0; nt < 4; nt++) {
                d0[nt] = bL1a; d1[nt] = bL1a; d2[nt] = bL1b; d3[nt] = bL1b;
            }
            #pragma unroll
            for (int kt = 0; kt < 4; kt++) {        // h0(t)
                #pragma unroll
                for (int nt = 0; nt < 4; nt++) {
                    int n = g8 + 8 * nt;
                    uint2 bb = *(const uint2*)(h0w + n * HS_STRIDE + kt * 8 + 2 * c4);
                    mma8(d0[nt], d1[nt], d2[nt], d3[nt],
                         A0[5 + kt], A1[5 + kt], A2[5 + kt], A3[5 + kt], bb.x, bb.y);
                }
            }
            #pragma unroll
            for (int kt = 0; kt < 4; kt++) {        // h1(t-1)
                #pragma unroll
                for (int nt = 0; nt < 4; nt++) {
                    int n = g8 + 8 * nt;
                    uint2 bb = *(const uint2*)(h1r + n * HS_STRIDE + kt * 8 + 2 * c4);
                    mma8(d0[nt], d1[nt], d2[nt], d3[nt],
                         A0[9 + kt], A1[9 + kt], A2[9 + kt], A3[9 + kt], bb.x, bb.y);
                }
            }

            // ===== L0-mm(t+1): bias + W_ih0 x(t+1) + W_hh0 h0(t) =====
            const float* xsrc;
            int lts;
            if (lt == CHUNK - 1) {
                if (tc + 1 < NCHUNK) {
                    asm volatile("cp.async.wait_group 0;");
                    __syncthreads();
                    xsrc = sm_x + (b ^ 1) * XBUF_F;
                    lts = 0;
                } else {
                    xsrc = cx; lts = CHUNK - 1;   // t=511: unused, clamp
                }
            } else {
                xsrc = cx; lts = lt + 1;
            }
            #pragma unroll
            for (int nt = 0; nt < 4; nt++) {
                g0[nt] = bL0a; g1[nt] = bL0a; g2[nt] = bL0b; g3[nt] = bL0b;
            }
            #pragma unroll
            for (int nt = 0; nt < 4; nt++) {        // x(t+1)
                int n = g8 + 8 * nt;
                uint32_t b0 = tf32c(xsrc[n * XS_STRIDE + lts * 6 + c4]);
                uint32_t b1 = (c4 < 2) ? tf32c(xsrc[n * XS_STRIDE + lts * 6 + 4 + c4]) : 0u;
                mma8(g0[nt], g1[nt], g2[nt], g3[nt], A0[0], A1[0], A2[0], A3[0], b0, b1);
            }
            #pragma unroll
            for (int kt = 1; kt < 5; kt++) {        // h0(t)
                #pragma unroll
                for (int nt = 0; nt < 4; nt++) {
                    int n = g8 + 8 * nt;
                    uint2 bb = *(const uint2*)(h0w + n * HS_STRIDE + (kt - 1) * 8 + 2 * c4);
                    mma8(g0[nt], g1[nt], g2[nt], g3[nt],
                         A0[kt], A1[kt], A2[kt], A3[kt], bb.x, bb.y);
                }
            }

            // ===== L1 activations (t) -> store h1(t) =====
            #pragma unroll
            for (int nt = 0; nt < 4; nt++) {
                float hv = act_combo(d0[nt], d1[nt], d2[nt], d3[nt], p4, c1s[nt]);
                *(uint32_t*)(h1w + (8 * nt + colC) * HS_STRIDE + physC) = tf32c(hv);
                if (t == T_STEPS - 1)
                    sm_x[(8 * nt + colC) * 33 + uC] = hv;   // f32 for LayerNorm
            }
        }
    }

    // ================= final LayerNorm over H=32 =================
    __syncthreads();
    {
        const float* hf = sm_x;
        float gam = ln_gamma[lane];
        float bet = ln_beta[lane];
        #pragma unroll
        for (int nb = 0; nb < 4; nb++) {
            int n = 4 * w + nb;
            float v = hf[n * 33 + lane];
            float s = v;
            #pragma unroll
            for (int o2 = 16; o2 > 0; o2 >>= 1) s += __shfl_xor_sync(0xffffffffu, s, o2);
            float mu = s * (1.0f / 32.0f);
            float dv = v - mu;
            float qq = dv * dv;
            #pragma unroll
            for (int o2 = 16; o2 > 0; o2 >>= 1) qq += __shfl_xor_sync(0xffffffffu, qq, o2);
            float var = qq * (1.0f / 32.0f);
            out[((size_t)blockIdx.x * NB + n) * 32 + lane] =
                dv * rsqrtf(var + 1e-5f) * gam + bet;
        }
    }
}

extern "C" void kernel_launch(void* const* d_in, const int* in_sizes, int n_in,
                              void* d_out, int out_size)
{
    const float* x      = (const float*)d_in[0];
    const float* W_ih0  = (const float*)d_in[1];
    const float* W_hh0  = (const float*)d_in[2];
    const float* b_ih0  = (const float*)d_in[3];
    const float* b_hh0  = (const float*)d_in[4];
    const float* W_ih1  = (const float*)d_in[5];
    const float* W_hh1  = (const float*)d_in[6];
    const float* b_ih1  = (const float*)d_in[7];
    const float* b_hh1  = (const float*)d_in[8];
    const float* ln_g   = (const float*)d_in[9];
    const float* ln_b   = (const float*)d_in[10];
    float* out = (float*)d_out;

    lstm_tc_kernel<<<NUM_CTAS, THREADS>>>(
        x, W_ih0, W_hh0, b_ih0, b_hh0, W_ih1, W_hh1, b_ih1, b_hh1,
        ln_g, ln_b, out);
}